// round 13
// baseline (speedup 1.0000x reference)
#include <cuda_runtime.h>
#include <cuda_bf16.h>
#include <math.h>
#include <stdint.h>

#define NN 100000
#define NE 1600000
#define NB 98  // ceil(NN/1024) scan blocks

// ---------------- scratch (static __device__, no allocation) ----------------
__device__ __align__(16) float g_agg1[(size_t)NN * 128]; // layer-1 neighbor means
__device__ __align__(16) float g_h[(size_t)NN * 128];    // layer-1 output (relu)
__device__ __align__(16) float g_tr[(size_t)NN * 80];    // [h@W2l | h@W2r] per node
// weights pre-transposed to [N][K] (K contiguous) and split into bf16 hi/lo
__device__ __align__(16) unsigned short g_w1h[128 * 256];
__device__ __align__(16) unsigned short g_w1lo[128 * 256];
__device__ __align__(16) unsigned short g_w2h[80 * 128];
__device__ __align__(16) unsigned short g_w2lo[80 * 128];
__device__ int g_src[NE];
__device__ int g_dst[NE];
__device__ int g_csr[NE];
__device__ int g_deg[NN];
__device__ int g_rowstart[NN];
__device__ int g_cursor[NN];
__device__ int g_scan[NN];
__device__ int g_bsum[NB];
__device__ int g_is64;

// ---------------- PTX helpers (sm_80-era, valid at compute_100) ----------------
static __device__ __forceinline__ uint32_t s2u(const void* p) {
    uint32_t a;
    asm("{ .reg .u64 t; cvta.to.shared.u64 t, %1; cvt.u32.u64 %0, t; }" : "=r"(a) : "l"(p));
    return a;
}
#define LDMX4(r0, r1, r2, r3, addr)                                             \
    asm volatile("ldmatrix.sync.aligned.m8n8.x4.shared.b16 {%0,%1,%2,%3}, [%4];" \
                 : "=r"(r0), "=r"(r1), "=r"(r2), "=r"(r3) : "r"(addr))
#define MMA16816(d, a0, a1, a2, a3, b0, b1)                                     \
    asm volatile("mma.sync.aligned.m16n8k16.row.col.f32.bf16.bf16.f32 "          \
                 "{%0,%1,%2,%3},{%4,%5,%6,%7},{%8,%9},{%0,%1,%2,%3};"            \
                 : "+f"((d)[0]), "+f"((d)[1]), "+f"((d)[2]), "+f"((d)[3])        \
                 : "r"(a0), "r"(a1), "r"(a2), "r"(a3), "r"(b0), "r"(b1))
#define CPASYNC16(dst, src)                                                      \
    asm volatile("cp.async.cg.shared.global [%0], [%1], 16;" :: "r"(dst), "l"(src))
#define CPASYNC_COMMIT() asm volatile("cp.async.commit_group;" ::: "memory")
#define CPASYNC_WAIT0()  asm volatile("cp.async.wait_group 0;" ::: "memory")

// ---------------- probe edge_index dtype (one warp, parallel) ----------------
__global__ void probe_k(const int* __restrict__ ei32) {
    int lane = threadIdx.x;
    int bad = 0;
#pragma unroll
    for (int i = 0; i < 4; i++)
        if (ei32[2 * (lane + 32 * i) + 1] != 0) bad = 1;
    bad = __any_sync(0xffffffffu, bad);
    if (lane == 0) g_is64 = bad ? 0 : 1;
}

// ---------------- setup: zero int scratch + pack/split weights ----------------
static __device__ __forceinline__ void split1(float v, unsigned short& h, unsigned short& l) {
    uint32_t u = __float_as_uint(v);
    h = (unsigned short)(u >> 16);
    float hf = __uint_as_float(u & 0xFFFF0000u);
    l = __bfloat16_as_ushort(__float2bfloat16(v - hf));
}
__global__ void setup_k(const float* __restrict__ W1l, const float* __restrict__ W1r,
                        const float* __restrict__ W2l, const float* __restrict__ W2r) {
    int i = blockIdx.x * blockDim.x + threadIdx.x;
    if (i < NN) { g_deg[i] = 0; g_cursor[i] = 0; }
    if (i < 128 * 256) { // w1: n = i/256, k = i%256
        int n = i >> 8, k = i & 255;
        float v = (k < 128) ? W1l[k * 128 + n] : W1r[(k - 128) * 128 + n];
        split1(v, g_w1h[i], g_w1lo[i]);
    }
    if (i < 80 * 128) { // w2: n = i/128, k = i%128
        int n = i >> 7, k = i & 127;
        float v = (n < 40) ? W2l[k * 40 + n] : W2r[k * 40 + (n - 40)];
        split1(v, g_w2h[i], g_w2lo[i]);
    }
}

// ---------------- edge convert + degree histogram ----------------
__global__ void convert_k(const void* __restrict__ ei) {
    int e = blockIdx.x * blockDim.x + threadIdx.x;
    if (e >= NE) return;
    int src, dst;
    if (g_is64) {
        src = (int)((const long long*)ei)[e];
        dst = (int)((const long long*)ei)[(long long)NE + e];
    } else {
        src = ((const int*)ei)[e];
        dst = ((const int*)ei)[NE + e];
    }
    g_src[e] = src;
    g_dst[e] = dst;
    atomicAdd(&g_deg[dst], 1);
}

// ---------------- prefix scan ----------------
__global__ __launch_bounds__(1024) void scan1_k() {
    __shared__ int s[1024];
    int t = threadIdx.x;
    int i = blockIdx.x * 1024 + t;
    int v = (i < NN) ? g_deg[i] : 0;
    s[t] = v;
    __syncthreads();
#pragma unroll
    for (int off = 1; off < 1024; off <<= 1) {
        int a = (t >= off) ? s[t - off] : 0;
        __syncthreads();
        s[t] += a;
        __syncthreads();
    }
    if (i < NN) g_scan[i] = s[t];
    if (t == 1023) g_bsum[blockIdx.x] = s[t];
}
__global__ void scan2_k() {
    __shared__ int s[128];
    int t = threadIdx.x;
    s[t] = (t < NB) ? g_bsum[t] : 0;
    __syncthreads();
#pragma unroll
    for (int off = 1; off < 128; off <<= 1) {
        int a = (t >= off) ? s[t - off] : 0;
        __syncthreads();
        s[t] += a;
        __syncthreads();
    }
    if (t < NB) g_bsum[t] = s[t];
}
__global__ void scan3_k() {
    int i = blockIdx.x * blockDim.x + threadIdx.x;
    if (i >= NN) return;
    int b = i >> 10;
    int base = (b > 0) ? g_bsum[b - 1] : 0;
    g_rowstart[i] = base + g_scan[i] - g_deg[i];
}

// ---------------- CSR fill ----------------
__global__ void fill_k() {
    int e = blockIdx.x * blockDim.x + threadIdx.x;
    if (e >= NE) return;
    int d = g_dst[e];
    int pos = g_rowstart[d] + atomicAdd(&g_cursor[d], 1);
    g_csr[pos] = g_src[e];
}

// ---------------- layer-1 gather-mean (unroll 4) ----------------
__global__ void agg1_k(const float* __restrict__ x) {
    int gt = blockIdx.x * blockDim.x + threadIdx.x;
    int n = gt >> 5;
    int lane = gt & 31;
    if (n >= NN) return;
    int start = g_rowstart[n];
    int deg = g_deg[n];
    float4 acc = make_float4(0.f, 0.f, 0.f, 0.f);
    int i = 0;
    for (; i + 3 < deg; i += 4) {
        int s0 = __ldg(g_csr + start + i);
        int s1 = __ldg(g_csr + start + i + 1);
        int s2 = __ldg(g_csr + start + i + 2);
        int s3 = __ldg(g_csr + start + i + 3);
        float4 v0 = ((const float4*)(x + (size_t)s0 * 128))[lane];
        float4 v1 = ((const float4*)(x + (size_t)s1 * 128))[lane];
        float4 v2 = ((const float4*)(x + (size_t)s2 * 128))[lane];
        float4 v3 = ((const float4*)(x + (size_t)s3 * 128))[lane];
        acc.x += (v0.x + v1.x) + (v2.x + v3.x);
        acc.y += (v0.y + v1.y) + (v2.y + v3.y);
        acc.z += (v0.z + v1.z) + (v2.z + v3.z);
        acc.w += (v0.w + v1.w) + (v2.w + v3.w);
    }
    for (; i < deg; i++) {
        int s0 = __ldg(g_csr + start + i);
        float4 v0 = ((const float4*)(x + (size_t)s0 * 128))[lane];
        acc.x += v0.x; acc.y += v0.y; acc.z += v0.z; acc.w += v0.w;
    }
    float inv = 1.0f / fmaxf((float)deg, 1.0f);
    acc.x *= inv; acc.y *= inv; acc.z *= inv; acc.w *= inv;
    ((float4*)(g_agg1 + (size_t)n * 128))[lane] = acc;
}

// ---------------- double-buffered mma.sync split-bf16 GEMM ----------------
// C[M,N] = [A0 | A1](M x KT fp32, split at col 128) @ B(KT x N), B = [N][KT]
// bf16 hi/lo. D += Ah*Bh + Ah*Bl + Al*Bh. B staged by cp.async; A prefetched
// into registers before the MMA section, converted+stored after it.
template <int N, int KT, bool RELU>
__global__ __launch_bounds__(256) void gemm_mma(
    int M, const float* __restrict__ A0, const float* __restrict__ A1,
    const unsigned short* __restrict__ Bh, const unsigned short* __restrict__ Bl,
    const float* __restrict__ bias, float* __restrict__ C) {
    constexpr int NT8 = N / 8;
    constexpr int KC = KT / 32;
    constexpr int ST = 40;
    // per-buffer layout (ushort offsets): Ah, Al, Bh, Bl
    constexpr int O_AL = 128 * ST;            // 5120
    constexpr int O_BH = 2 * 128 * ST;        // 10240
    constexpr int O_BL = O_BH + N * ST;
    constexpr int CHUNK = O_BH + 2 * N * ST;  // per-buffer ushorts
    extern __shared__ unsigned short sm[];

    const int tid = threadIdx.x;
    const int wid = tid >> 5, lane = tid & 31;
    const int rowBase = blockIdx.x * 128;

    float acc[NT8][4];
#pragma unroll
    for (int t = 0; t < NT8; t++)
#pragma unroll
        for (int q = 0; q < 4; q++) acc[t][q] = 0.f;

    const int arow = tid >> 1;
    const int ach = (tid & 1) * 16;
    const int gr_a = rowBase + arow;
    const bool a_ok = (gr_a < M);

    // ---- helpers as lambdas ----
    auto stageB = [&](int bufbase, int gk) {
        for (int idx = tid; idx < N * 4; idx += 256) {
            int n = idx >> 2, q = idx & 3;
            uint32_t dh = s2u(&sm[bufbase + O_BH + n * ST + q * 8]);
            uint32_t dl = s2u(&sm[bufbase + O_BL + n * ST + q * 8]);
            CPASYNC16(dh, Bh + (size_t)n * KT + gk + q * 8);
            CPASYNC16(dl, Bl + (size_t)n * KT + gk + q * 8);
        }
    };
    auto loadA = [&](int gk, float4* v) {
        const float* Ap = (gk < 128) ? (A0 + (size_t)gr_a * 128 + gk + ach)
                                     : (A1 + (size_t)gr_a * 128 + (gk - 128) + ach);
#pragma unroll
        for (int i = 0; i < 4; i++)
            v[i] = a_ok ? *(const float4*)(Ap + i * 4) : make_float4(0.f, 0.f, 0.f, 0.f);
    };
    auto storeA = [&](int bufbase, const float4* v) {
#pragma unroll
        for (int i = 0; i < 4; i++) {
            uint32_t ux = __float_as_uint(v[i].x), uy = __float_as_uint(v[i].y);
            uint32_t uz = __float_as_uint(v[i].z), uw = __float_as_uint(v[i].w);
            uint2 hv, lv;
            hv.x = (ux >> 16) | (uy & 0xFFFF0000u);
            hv.y = (uz >> 16) | (uw & 0xFFFF0000u);
            unsigned short l0 = __bfloat16_as_ushort(
                __float2bfloat16(v[i].x - __uint_as_float(ux & 0xFFFF0000u)));
            unsigned short l1 = __bfloat16_as_ushort(
                __float2bfloat16(v[i].y - __uint_as_float(uy & 0xFFFF0000u)));
            unsigned short l2 = __bfloat16_as_ushort(
                __float2bfloat16(v[i].z - __uint_as_float(uz & 0xFFFF0000u)));
            unsigned short l3 = __bfloat16_as_ushort(
                __float2bfloat16(v[i].w - __uint_as_float(uw & 0xFFFF0000u)));
            lv.x = (uint32_t)l0 | ((uint32_t)l1 << 16);
            lv.y = (uint32_t)l2 | ((uint32_t)l3 << 16);
            *(uint2*)&sm[bufbase + arow * ST + ach + i * 4] = hv;
            *(uint2*)&sm[bufbase + O_AL + arow * ST + ach + i * 4] = lv;
        }
    };

    // ---- prologue: stage chunk 0 into buffer 0 ----
    {
        stageB(0, 0);
        CPASYNC_COMMIT();
        float4 v[4];
        loadA(0, v);
        storeA(0, v);
        CPASYNC_WAIT0();
        __syncthreads();
    }

    int bufbase = 0;
    for (int c = 0; c < KC; c++) {
        const int nbuf = bufbase ^ CHUNK;
        const bool has_next = (c + 1 < KC);
        float4 vnext[4];
        if (has_next) {
            stageB(nbuf, (c + 1) * 32);
            CPASYNC_COMMIT();
            loadA((c + 1) * 32, vnext);
        }
        // ---- compute on current buffer ----
#pragma unroll
        for (int ks = 0; ks < 2; ks++) {
            const int kb = ks * 16;
            const int am = wid * 16 + (lane & 7) + ((lane >> 3) & 1) * 8;
            const int ak = kb + (lane >> 4) * 8;
            uint32_t ah0, ah1, ah2, ah3, al0, al1, al2, al3;
            {
                uint32_t addr = s2u(&sm[bufbase + am * ST + ak]);
                LDMX4(ah0, ah1, ah2, ah3, addr);
                addr = s2u(&sm[bufbase + O_AL + am * ST + ak]);
                LDMX4(al0, al1, al2, al3, addr);
            }
            const int bn = (lane & 7) + (lane >> 4) * 8;
            const int bk = kb + ((lane >> 3) & 1) * 8;
#pragma unroll
            for (int p = 0; p < NT8 / 2; p++) {
                uint32_t bh0, bh1, bh2, bh3, bl0_, bl1_, bl2_, bl3_;
                uint32_t addr = s2u(&sm[bufbase + O_BH + (p * 16 + bn) * ST + bk]);
                LDMX4(bh0, bh1, bh2, bh3, addr);
                addr = s2u(&sm[bufbase + O_BL + (p * 16 + bn) * ST + bk]);
                LDMX4(bl0_, bl1_, bl2_, bl3_, addr);
                MMA16816(acc[2 * p + 0], ah0, ah1, ah2, ah3, bh0, bh1);
                MMA16816(acc[2 * p + 0], ah0, ah1, ah2, ah3, bl0_, bl1_);
                MMA16816(acc[2 * p + 0], al0, al1, al2, al3, bh0, bh1);
                MMA16816(acc[2 * p + 1], ah0, ah1, ah2, ah3, bh2, bh3);
                MMA16816(acc[2 * p + 1], ah0, ah1, ah2, ah3, bl2_, bl3_);
                MMA16816(acc[2 * p + 1], al0, al1, al2, al3, bh2, bh3);
            }
        }
        if (has_next) {
            storeA(nbuf, vnext);
            CPASYNC_WAIT0();
        }
        __syncthreads();
        bufbase = nbuf;
    }

    // ---- epilogue ----
    const int r0 = rowBase + wid * 16 + (lane >> 2);
    const int col0 = (lane & 3) * 2;
#pragma unroll
    for (int t = 0; t < NT8; t++) {
        int col = t * 8 + col0;
        float2 v0 = make_float2(acc[t][0], acc[t][1]);
        float2 v1 = make_float2(acc[t][2], acc[t][3]);
        if (RELU) {
            float b0v = __ldg(bias + col), b1v = __ldg(bias + col + 1);
            v0.x = fmaxf(v0.x + b0v, 0.f); v0.y = fmaxf(v0.y + b1v, 0.f);
            v1.x = fmaxf(v1.x + b0v, 0.f); v1.y = fmaxf(v1.y + b1v, 0.f);
        }
        if (r0 < M)     *(float2*)(C + (size_t)r0 * N + col) = v0;
        if (r0 + 8 < M) *(float2*)(C + (size_t)(r0 + 8) * N + col) = v1;
    }
}

// ---------------- fused layer-2 gather-mean + root + bias + log_softmax ----------------
__global__ void final_k(const float* __restrict__ b2, float* __restrict__ out) {
    int gt = blockIdx.x * blockDim.x + threadIdx.x;
    int n = gt >> 5;
    int lane = gt & 31;
    if (n >= NN) return;
    int start = g_rowstart[n];
    int deg = g_deg[n];
    int c = lane * 2;
    float2 acc = make_float2(0.f, 0.f);
    if (lane < 20) {
        int i = 0;
        for (; i + 1 < deg; i += 2) {
            int s0 = __ldg(g_csr + start + i);
            int s1 = __ldg(g_csr + start + i + 1);
            float2 v0 = *(const float2*)(g_tr + (size_t)s0 * 80 + c);
            float2 v1 = *(const float2*)(g_tr + (size_t)s1 * 80 + c);
            acc.x += v0.x + v1.x;
            acc.y += v0.y + v1.y;
        }
        if (i < deg) {
            int s0 = __ldg(g_csr + start + i);
            float2 v0 = *(const float2*)(g_tr + (size_t)s0 * 80 + c);
            acc.x += v0.x;
            acc.y += v0.y;
        }
    }
    float inv = 1.0f / fmaxf((float)deg, 1.0f);
    float e0 = -3.4e38f, e1 = -3.4e38f;
    if (lane < 20) {
        e0 = acc.x * inv + g_tr[(size_t)n * 80 + 40 + c] + b2[c];
        e1 = acc.y * inv + g_tr[(size_t)n * 80 + 41 + c] + b2[c + 1];
    }
    float m = fmaxf(e0, e1);
#pragma unroll
    for (int o = 16; o > 0; o >>= 1) m = fmaxf(m, __shfl_xor_sync(0xffffffffu, m, o));
    float s = (lane < 20) ? (expf(e0 - m) + expf(e1 - m)) : 0.f;
#pragma unroll
    for (int o = 16; o > 0; o >>= 1) s += __shfl_xor_sync(0xffffffffu, s, o);
    float lse = m + logf(s);
    if (lane < 20) {
        float2 o2;
        o2.x = e0 - lse;
        o2.y = e1 - lse;
        *(float2*)(out + (size_t)n * 40 + c) = o2;
    }
}

// ---------------- launch ----------------
extern "C" void kernel_launch(void* const* d_in, const int* in_sizes, int n_in,
                              void* d_out, int out_size) {
    const float* x   = (const float*)d_in[0];
    const void* ei   = d_in[1];
    const float* W1l = (const float*)d_in[2];
    const float* W1r = (const float*)d_in[3];
    const float* b1  = (const float*)d_in[4];
    const float* W2l = (const float*)d_in[5];
    const float* W2r = (const float*)d_in[6];
    const float* b2  = (const float*)d_in[7];
    float* out       = (float*)d_out;

    float *agg1, *h, *tr;
    unsigned short *w1h, *w1lo, *w2h, *w2lo;
    cudaGetSymbolAddress((void**)&agg1, g_agg1);
    cudaGetSymbolAddress((void**)&h, g_h);
    cudaGetSymbolAddress((void**)&tr, g_tr);
    cudaGetSymbolAddress((void**)&w1h, g_w1h);
    cudaGetSymbolAddress((void**)&w1lo, g_w1lo);
    cudaGetSymbolAddress((void**)&w2h, g_w2h);
    cudaGetSymbolAddress((void**)&w2lo, g_w2lo);

    const int mtiles = (NN + 127) / 128; // 782
    // dynamic smem: 2 buffers of (2*128*ST + 2*N*ST) ushorts
    const int SMEM1 = 2 * (2 * 128 * 40 + 2 * 128 * 40) * 2; // 81920 B
    const int SMEM2 = 2 * (2 * 128 * 40 + 2 * 80 * 40) * 2;  // 66560 B
    cudaFuncSetAttribute(gemm_mma<128, 256, true>,
                         cudaFuncAttributeMaxDynamicSharedMemorySize, SMEM1);
    cudaFuncSetAttribute(gemm_mma<80, 128, false>,
                         cudaFuncAttributeMaxDynamicSharedMemorySize, SMEM2);

    probe_k<<<1, 32>>>((const int*)ei);
    setup_k<<<(NN + 255) / 256, 256>>>(W1l, W1r, W2l, W2r);
    convert_k<<<(NE + 255) / 256, 256>>>(ei);
    scan1_k<<<NB, 1024>>>();
    scan2_k<<<1, 128>>>();
    scan3_k<<<(NN + 255) / 256, 256>>>();
    fill_k<<<(NE + 255) / 256, 256>>>();
    agg1_k<<<(NN * 32 + 255) / 256, 256>>>(x);
    gemm_mma<128, 256, true><<<mtiles, 256, SMEM1>>>(NN, agg1, x, w1h, w1lo, b1, h);
    gemm_mma<80, 128, false><<<mtiles, 256, SMEM2>>>(NN, h, h, w2h, w2lo, nullptr, tr);
    final_k<<<(NN * 32 + 255) / 256, 256>>>(b2, out);
}

// round 14
// speedup vs baseline: 1.0878x; 1.0878x over previous
#include <cuda_runtime.h>
#include <cuda_bf16.h>
#include <cuda_fp16.h>
#include <math.h>
#include <stdint.h>

#define NN 100000
#define NE 1600000
#define NB 98  // ceil(NN/1024) scan blocks

// ---------------- scratch (static __device__, no allocation) ----------------
__device__ __align__(16) float g_agg1[(size_t)NN * 128]; // layer-1 neighbor means
__device__ __align__(16) float g_h[(size_t)NN * 128];    // layer-1 output (relu)
__device__ __align__(16) float g_tr[(size_t)NN * 80];    // [h@W2l | h@W2r] per node
__device__ __align__(16) __half g_xh[(size_t)NN * 128];  // fp16 copy of x (gather operand)
__device__ __align__(16) __half g_trh[(size_t)NN * 40];  // fp16 copy of tr[:, 0:40]
// weights pre-transposed to [N][K] (K contiguous) and split into bf16 hi/lo
__device__ __align__(16) unsigned short g_w1h[128 * 256];
__device__ __align__(16) unsigned short g_w1lo[128 * 256];
__device__ __align__(16) unsigned short g_w2h[80 * 128];
__device__ __align__(16) unsigned short g_w2lo[80 * 128];
__device__ int g_src[NE];
__device__ int g_dst[NE];
__device__ int g_csr[NE];
__device__ int g_deg[NN];
__device__ int g_rowstart[NN];
__device__ int g_cursor[NN];
__device__ int g_scan[NN];
__device__ int g_bsum[NB];
__device__ int g_is64;

// ---------------- PTX helpers (sm_80-era, valid at compute_100) ----------------
static __device__ __forceinline__ uint32_t s2u(const void* p) {
    uint32_t a;
    asm("{ .reg .u64 t; cvta.to.shared.u64 t, %1; cvt.u32.u64 %0, t; }" : "=r"(a) : "l"(p));
    return a;
}
#define LDMX4(r0, r1, r2, r3, addr)                                             \
    asm volatile("ldmatrix.sync.aligned.m8n8.x4.shared.b16 {%0,%1,%2,%3}, [%4];" \
                 : "=r"(r0), "=r"(r1), "=r"(r2), "=r"(r3) : "r"(addr))
#define MMA16816(d, a0, a1, a2, a3, b0, b1)                                     \
    asm volatile("mma.sync.aligned.m16n8k16.row.col.f32.bf16.bf16.f32 "          \
                 "{%0,%1,%2,%3},{%4,%5,%6,%7},{%8,%9},{%0,%1,%2,%3};"            \
                 : "+f"((d)[0]), "+f"((d)[1]), "+f"((d)[2]), "+f"((d)[3])        \
                 : "r"(a0), "r"(a1), "r"(a2), "r"(a3), "r"(b0), "r"(b1))

// ---------------- probe edge_index dtype (one warp, parallel) ----------------
__global__ void probe_k(const int* __restrict__ ei32) {
    int lane = threadIdx.x;
    int bad = 0;
#pragma unroll
    for (int i = 0; i < 4; i++)
        if (ei32[2 * (lane + 32 * i) + 1] != 0) bad = 1;
    bad = __any_sync(0xffffffffu, bad);
    if (lane == 0) g_is64 = bad ? 0 : 1;
}

// ---------------- setup: zero scratch + split weights + x -> fp16 ----------------
static __device__ __forceinline__ void split1(float v, unsigned short& h, unsigned short& l) {
    uint32_t u = __float_as_uint(v);
    h = (unsigned short)(u >> 16);
    float hf = __uint_as_float(u & 0xFFFF0000u);
    l = __bfloat16_as_ushort(__float2bfloat16(v - hf));
}
__global__ void setup_k(const float* __restrict__ x,
                        const float* __restrict__ W1l, const float* __restrict__ W1r,
                        const float* __restrict__ W2l, const float* __restrict__ W2r) {
    int i = blockIdx.x * blockDim.x + threadIdx.x; // NN*32 threads
    if (i < NN) { g_deg[i] = 0; g_cursor[i] = 0; }
    if (i < 128 * 256) { // w1: n = i/256, k = i%256
        int n = i >> 8, k = i & 255;
        float v = (k < 128) ? W1l[k * 128 + n] : W1r[(k - 128) * 128 + n];
        split1(v, g_w1h[i], g_w1lo[i]);
    }
    if (i < 80 * 128) { // w2: n = i/128, k = i%128
        int n = i >> 7, k = i & 127;
        float v = (n < 40) ? W2l[k * 40 + n] : W2r[k * 40 + (n - 40)];
        split1(v, g_w2h[i], g_w2lo[i]);
    }
    if (i < NN * 32) { // x -> fp16, 4 elems per thread
        float4 v = ((const float4*)x)[i];
        __half2 h0 = __floats2half2_rn(v.x, v.y);
        __half2 h1 = __floats2half2_rn(v.z, v.w);
        uint2 u;
        u.x = *(uint32_t*)&h0;
        u.y = *(uint32_t*)&h1;
        *(uint2*)(g_xh + (size_t)i * 4) = u;
    }
}

// ---------------- edge convert + degree histogram ----------------
__global__ void convert_k(const void* __restrict__ ei) {
    int e = blockIdx.x * blockDim.x + threadIdx.x;
    if (e >= NE) return;
    int src, dst;
    if (g_is64) {
        src = (int)((const long long*)ei)[e];
        dst = (int)((const long long*)ei)[(long long)NE + e];
    } else {
        src = ((const int*)ei)[e];
        dst = ((const int*)ei)[NE + e];
    }
    g_src[e] = src;
    g_dst[e] = dst;
    atomicAdd(&g_deg[dst], 1);
}

// ---------------- prefix scan ----------------
__global__ __launch_bounds__(1024) void scan1_k() {
    __shared__ int s[1024];
    int t = threadIdx.x;
    int i = blockIdx.x * 1024 + t;
    int v = (i < NN) ? g_deg[i] : 0;
    s[t] = v;
    __syncthreads();
#pragma unroll
    for (int off = 1; off < 1024; off <<= 1) {
        int a = (t >= off) ? s[t - off] : 0;
        __syncthreads();
        s[t] += a;
        __syncthreads();
    }
    if (i < NN) g_scan[i] = s[t];
    if (t == 1023) g_bsum[blockIdx.x] = s[t];
}
__global__ void scan2_k() {
    __shared__ int s[128];
    int t = threadIdx.x;
    s[t] = (t < NB) ? g_bsum[t] : 0;
    __syncthreads();
#pragma unroll
    for (int off = 1; off < 128; off <<= 1) {
        int a = (t >= off) ? s[t - off] : 0;
        __syncthreads();
        s[t] += a;
        __syncthreads();
    }
    if (t < NB) g_bsum[t] = s[t];
}
__global__ void scan3_k() {
    int i = blockIdx.x * blockDim.x + threadIdx.x;
    if (i >= NN) return;
    int b = i >> 10;
    int base = (b > 0) ? g_bsum[b - 1] : 0;
    g_rowstart[i] = base + g_scan[i] - g_deg[i];
}

// ---------------- CSR fill ----------------
__global__ void fill_k() {
    int e = blockIdx.x * blockDim.x + threadIdx.x;
    if (e >= NE) return;
    int d = g_dst[e];
    int pos = g_rowstart[d] + atomicAdd(&g_cursor[d], 1);
    g_csr[pos] = g_src[e];
}

// ---------------- layer-1 gather-mean from fp16 x (unroll 4) ----------------
// one warp per node; lane owns 4 channels = one uint2 (4 halves) per neighbor
__global__ void agg1_k() {
    int gt = blockIdx.x * blockDim.x + threadIdx.x;
    int n = gt >> 5;
    int lane = gt & 31;
    if (n >= NN) return;
    int start = g_rowstart[n];
    int deg = g_deg[n];
    float4 acc = make_float4(0.f, 0.f, 0.f, 0.f);
    int i = 0;
    for (; i + 3 < deg; i += 4) {
        int s0 = __ldg(g_csr + start + i);
        int s1 = __ldg(g_csr + start + i + 1);
        int s2 = __ldg(g_csr + start + i + 2);
        int s3 = __ldg(g_csr + start + i + 3);
        uint2 r0 = ((const uint2*)(g_xh + (size_t)s0 * 128))[lane];
        uint2 r1 = ((const uint2*)(g_xh + (size_t)s1 * 128))[lane];
        uint2 r2 = ((const uint2*)(g_xh + (size_t)s2 * 128))[lane];
        uint2 r3 = ((const uint2*)(g_xh + (size_t)s3 * 128))[lane];
        float2 a0 = __half22float2(*(__half2*)&r0.x), b0 = __half22float2(*(__half2*)&r0.y);
        float2 a1 = __half22float2(*(__half2*)&r1.x), b1 = __half22float2(*(__half2*)&r1.y);
        float2 a2 = __half22float2(*(__half2*)&r2.x), b2 = __half22float2(*(__half2*)&r2.y);
        float2 a3 = __half22float2(*(__half2*)&r3.x), b3 = __half22float2(*(__half2*)&r3.y);
        acc.x += (a0.x + a1.x) + (a2.x + a3.x);
        acc.y += (a0.y + a1.y) + (a2.y + a3.y);
        acc.z += (b0.x + b1.x) + (b2.x + b3.x);
        acc.w += (b0.y + b1.y) + (b2.y + b3.y);
    }
    for (; i < deg; i++) {
        int s0 = __ldg(g_csr + start + i);
        uint2 r0 = ((const uint2*)(g_xh + (size_t)s0 * 128))[lane];
        float2 a0 = __half22float2(*(__half2*)&r0.x), b0 = __half22float2(*(__half2*)&r0.y);
        acc.x += a0.x; acc.y += a0.y; acc.z += b0.x; acc.w += b0.y;
    }
    float inv = 1.0f / fmaxf((float)deg, 1.0f);
    acc.x *= inv; acc.y *= inv; acc.z *= inv; acc.w *= inv;
    ((float4*)(g_agg1 + (size_t)n * 128))[lane] = acc;
}

// ---------------- mma.sync split-bf16 GEMM (proven R9 structure) ----------------
// C[M,N] = [A0 | A1](M x KT fp32, split at col 128) @ B(KT x N), B = [N][KT]
// bf16 hi/lo. D += Ah*Bh + Ah*Bl + Al*Bh. WRITEH: also emit fp16 copy of
// cols 0..39 into Ch (row stride 40).
template <int N, int KT, bool RELU, bool WRITEH>
__global__ __launch_bounds__(256) void gemm_mma(
    int M, const float* __restrict__ A0, const float* __restrict__ A1,
    const unsigned short* __restrict__ Bh, const unsigned short* __restrict__ Bl,
    const float* __restrict__ bias, float* __restrict__ C, __half* __restrict__ Ch) {
    constexpr int NT8 = N / 8;
    constexpr int KC = KT / 32;
    constexpr int ST = 40;
    __shared__ unsigned short sAh[128 * ST], sAl[128 * ST];
    __shared__ unsigned short sBh[N * ST], sBl[N * ST];

    const int tid = threadIdx.x;
    const int wid = tid >> 5, lane = tid & 31;
    const int rowBase = blockIdx.x * 128;

    float acc[NT8][4];
#pragma unroll
    for (int t = 0; t < NT8; t++)
#pragma unroll
        for (int q = 0; q < 4; q++) acc[t][q] = 0.f;

    const int arow = tid >> 1;
    const int ach = (tid & 1) * 16;
    const int gr_a = rowBase + arow;

    for (int c = 0; c < KC; c++) {
        const int gk = c * 32;
        const float* Ap = (gk < 128) ? (A0 + (size_t)gr_a * 128 + gk + ach)
                                     : (A1 + (size_t)gr_a * 128 + (gk - 128) + ach);
#pragma unroll
        for (int i = 0; i < 4; i++) {
            float4 v = (gr_a < M) ? *(const float4*)(Ap + i * 4)
                                  : make_float4(0.f, 0.f, 0.f, 0.f);
            uint32_t ux = __float_as_uint(v.x), uy = __float_as_uint(v.y);
            uint32_t uz = __float_as_uint(v.z), uw = __float_as_uint(v.w);
            uint2 hv, lv;
            hv.x = (ux >> 16) | (uy & 0xFFFF0000u);
            hv.y = (uz >> 16) | (uw & 0xFFFF0000u);
            unsigned short l0 = __bfloat16_as_ushort(
                __float2bfloat16(v.x - __uint_as_float(ux & 0xFFFF0000u)));
            unsigned short l1 = __bfloat16_as_ushort(
                __float2bfloat16(v.y - __uint_as_float(uy & 0xFFFF0000u)));
            unsigned short l2 = __bfloat16_as_ushort(
                __float2bfloat16(v.z - __uint_as_float(uz & 0xFFFF0000u)));
            unsigned short l3 = __bfloat16_as_ushort(
                __float2bfloat16(v.w - __uint_as_float(uw & 0xFFFF0000u)));
            lv.x = (uint32_t)l0 | ((uint32_t)l1 << 16);
            lv.y = (uint32_t)l2 | ((uint32_t)l3 << 16);
            *(uint2*)&sAh[arow * ST + ach + i * 4] = hv;
            *(uint2*)&sAl[arow * ST + ach + i * 4] = lv;
        }
        for (int idx = tid; idx < N * 4; idx += 256) {
            int n = idx >> 2, q = idx & 3;
            *(uint4*)&sBh[n * ST + q * 8] = *(const uint4*)(Bh + (size_t)n * KT + gk + q * 8);
            *(uint4*)&sBl[n * ST + q * 8] = *(const uint4*)(Bl + (size_t)n * KT + gk + q * 8);
        }
        __syncthreads();
#pragma unroll
        for (int ks = 0; ks < 2; ks++) {
            const int kb = ks * 16;
            const int am = wid * 16 + (lane & 7) + ((lane >> 3) & 1) * 8;
            const int ak = kb + (lane >> 4) * 8;
            uint32_t ah0, ah1, ah2, ah3, al0, al1, al2, al3;
            {
                uint32_t addr = s2u(&sAh[am * ST + ak]);
                LDMX4(ah0, ah1, ah2, ah3, addr);
                addr = s2u(&sAl[am * ST + ak]);
                LDMX4(al0, al1, al2, al3, addr);
            }
            const int bn = (lane & 7) + (lane >> 4) * 8;
            const int bk = kb + ((lane >> 3) & 1) * 8;
#pragma unroll
            for (int p = 0; p < NT8 / 2; p++) {
                uint32_t bh0, bh1, bh2, bh3, bl0_, bl1_, bl2_, bl3_;
                uint32_t addr = s2u(&sBh[(p * 16 + bn) * ST + bk]);
                LDMX4(bh0, bh1, bh2, bh3, addr);
                addr = s2u(&sBl[(p * 16 + bn) * ST + bk]);
                LDMX4(bl0_, bl1_, bl2_, bl3_, addr);
                MMA16816(acc[2 * p + 0], ah0, ah1, ah2, ah3, bh0, bh1);
                MMA16816(acc[2 * p + 0], ah0, ah1, ah2, ah3, bl0_, bl1_);
                MMA16816(acc[2 * p + 0], al0, al1, al2, al3, bh0, bh1);
                MMA16816(acc[2 * p + 1], ah0, ah1, ah2, ah3, bh2, bh3);
                MMA16816(acc[2 * p + 1], ah0, ah1, ah2, ah3, bl2_, bl3_);
                MMA16816(acc[2 * p + 1], al0, al1, al2, al3, bh2, bh3);
            }
        }
        __syncthreads();
    }
    const int r0 = rowBase + wid * 16 + (lane >> 2);
    const int col0 = (lane & 3) * 2;
#pragma unroll
    for (int t = 0; t < NT8; t++) {
        int col = t * 8 + col0;
        float2 v0 = make_float2(acc[t][0], acc[t][1]);
        float2 v1 = make_float2(acc[t][2], acc[t][3]);
        if (RELU) {
            float b0v = __ldg(bias + col), b1v = __ldg(bias + col + 1);
            v0.x = fmaxf(v0.x + b0v, 0.f); v0.y = fmaxf(v0.y + b1v, 0.f);
            v1.x = fmaxf(v1.x + b0v, 0.f); v1.y = fmaxf(v1.y + b1v, 0.f);
        }
        if (r0 < M) {
            *(float2*)(C + (size_t)r0 * N + col) = v0;
            if (WRITEH && col < 40) {
                __half2 hh = __floats2half2_rn(v0.x, v0.y);
                *(uint32_t*)(Ch + (size_t)r0 * 40 + col) = *(uint32_t*)&hh;
            }
        }
        if (r0 + 8 < M) {
            *(float2*)(C + (size_t)(r0 + 8) * N + col) = v1;
            if (WRITEH && col < 40) {
                __half2 hh = __floats2half2_rn(v1.x, v1.y);
                *(uint32_t*)(Ch + (size_t)(r0 + 8) * 40 + col) = *(uint32_t*)&hh;
            }
        }
    }
}

// ---------------- fused layer-2 gather-mean (fp16) + root + bias + log_softmax ----------------
__global__ void final_k(const float* __restrict__ b2, float* __restrict__ out) {
    int gt = blockIdx.x * blockDim.x + threadIdx.x;
    int n = gt >> 5;
    int lane = gt & 31;
    if (n >= NN) return;
    int start = g_rowstart[n];
    int deg = g_deg[n];
    int c = lane * 2;
    float2 acc = make_float2(0.f, 0.f);
    if (lane < 20) {
        int i = 0;
        for (; i + 1 < deg; i += 2) {
            int s0 = __ldg(g_csr + start + i);
            int s1 = __ldg(g_csr + start + i + 1);
            uint32_t r0 = *(const uint32_t*)(g_trh + (size_t)s0 * 40 + c);
            uint32_t r1 = *(const uint32_t*)(g_trh + (size_t)s1 * 40 + c);
            float2 v0 = __half22float2(*(__half2*)&r0);
            float2 v1 = __half22float2(*(__half2*)&r1);
            acc.x += v0.x + v1.x;
            acc.y += v0.y + v1.y;
        }
        if (i < deg) {
            int s0 = __ldg(g_csr + start + i);
            uint32_t r0 = *(const uint32_t*)(g_trh + (size_t)s0 * 40 + c);
            float2 v0 = __half22float2(*(__half2*)&r0);
            acc.x += v0.x;
            acc.y += v0.y;
        }
    }
    float inv = 1.0f / fmaxf((float)deg, 1.0f);
    float e0 = -3.4e38f, e1 = -3.4e38f;
    if (lane < 20) {
        e0 = acc.x * inv + g_tr[(size_t)n * 80 + 40 + c] + b2[c];
        e1 = acc.y * inv + g_tr[(size_t)n * 80 + 41 + c] + b2[c + 1];
    }
    float m = fmaxf(e0, e1);
#pragma unroll
    for (int o = 16; o > 0; o >>= 1) m = fmaxf(m, __shfl_xor_sync(0xffffffffu, m, o));
    float s = (lane < 20) ? (expf(e0 - m) + expf(e1 - m)) : 0.f;
#pragma unroll
    for (int o = 16; o > 0; o >>= 1) s += __shfl_xor_sync(0xffffffffu, s, o);
    float lse = m + logf(s);
    if (lane < 20) {
        float2 o2;
        o2.x = e0 - lse;
        o2.y = e1 - lse;
        *(float2*)(out + (size_t)n * 40 + c) = o2;
    }
}

// ---------------- launch ----------------
extern "C" void kernel_launch(void* const* d_in, const int* in_sizes, int n_in,
                              void* d_out, int out_size) {
    const float* x   = (const float*)d_in[0];
    const void* ei   = d_in[1];
    const float* W1l = (const float*)d_in[2];
    const float* W1r = (const float*)d_in[3];
    const float* b1  = (const float*)d_in[4];
    const float* W2l = (const float*)d_in[5];
    const float* W2r = (const float*)d_in[6];
    const float* b2  = (const float*)d_in[7];
    float* out       = (float*)d_out;

    float *agg1, *h, *tr;
    __half* trh;
    unsigned short *w1h, *w1lo, *w2h, *w2lo;
    cudaGetSymbolAddress((void**)&agg1, g_agg1);
    cudaGetSymbolAddress((void**)&h, g_h);
    cudaGetSymbolAddress((void**)&tr, g_tr);
    cudaGetSymbolAddress((void**)&trh, g_trh);
    cudaGetSymbolAddress((void**)&w1h, g_w1h);
    cudaGetSymbolAddress((void**)&w1lo, g_w1lo);
    cudaGetSymbolAddress((void**)&w2h, g_w2h);
    cudaGetSymbolAddress((void**)&w2lo, g_w2lo);

    const int mtiles = (NN + 127) / 128; // 782

    probe_k<<<1, 32>>>((const int*)ei);
    setup_k<<<(NN * 32 + 255) / 256, 256>>>(x, W1l, W1r, W2l, W2r);
    convert_k<<<(NE + 255) / 256, 256>>>(ei);
    scan1_k<<<NB, 1024>>>();
    scan2_k<<<1, 128>>>();
    scan3_k<<<(NN + 255) / 256, 256>>>();
    fill_k<<<(NE + 255) / 256, 256>>>();
    agg1_k<<<(NN * 32 + 255) / 256, 256>>>();
    gemm_mma<128, 256, true, false><<<mtiles, 256>>>(NN, agg1, x, w1h, w1lo, b1, h, nullptr);
    gemm_mma<80, 128, false, true><<<mtiles, 256>>>(NN, h, h, w2h, w2lo, nullptr, tr, trh);
    final_k<<<(NN * 32 + 255) / 256, 256>>>(b2, out);
}

// round 15
// speedup vs baseline: 1.2532x; 1.1521x over previous
#include <cuda_runtime.h>
#include <cuda_fp16.h>
#include <math.h>
#include <stdint.h>

#define NN 100000
#define NE 1600000
#define NB 98  // ceil(NN/1024) scan blocks

// ---------------- scratch (static __device__, no allocation) ----------------
__device__ __align__(16) __half g_xh[(size_t)NN * 128];   // fp16 copy of x
__device__ __align__(16) __half g_a1h[(size_t)NN * 128];  // layer-1 neighbor means (fp16)
__device__ __align__(16) __half g_hh[(size_t)NN * 128];   // h = relu(...) (fp16)
__device__ __align__(16) float g_tr[(size_t)NN * 80];     // [h@W2l | h@W2r] (fp32, root term)
__device__ __align__(16) __half g_trh[(size_t)NN * 40];   // fp16 copy of tr[:, 0:40] (gather)
// weights pre-transposed to [N][K] (K contiguous), split into fp16 hi/lo
__device__ __align__(16) unsigned short g_w1h[128 * 256];
__device__ __align__(16) unsigned short g_w1lo[128 * 256];
__device__ __align__(16) unsigned short g_w2h[80 * 128];
__device__ __align__(16) unsigned short g_w2lo[80 * 128];
__device__ int g_src[NE];
__device__ int g_dst[NE];
__device__ int g_csr[NE];
__device__ int g_deg[NN];
__device__ int g_rowstart[NN];
__device__ int g_cursor[NN];
__device__ int g_scan[NN];
__device__ int g_bsum[NB];
__device__ int g_is64;

// ---------------- PTX helpers (sm_80-era, valid at compute_100) ----------------
static __device__ __forceinline__ uint32_t s2u(const void* p) {
    uint32_t a;
    asm("{ .reg .u64 t; cvta.to.shared.u64 t, %1; cvt.u32.u64 %0, t; }" : "=r"(a) : "l"(p));
    return a;
}
#define LDMX4(r0, r1, r2, r3, addr)                                             \
    asm volatile("ldmatrix.sync.aligned.m8n8.x4.shared.b16 {%0,%1,%2,%3}, [%4];" \
                 : "=r"(r0), "=r"(r1), "=r"(r2), "=r"(r3) : "r"(addr))
#define MMAF16(d, a0, a1, a2, a3, b0, b1)                                        \
    asm volatile("mma.sync.aligned.m16n8k16.row.col.f32.f16.f16.f32 "            \
                 "{%0,%1,%2,%3},{%4,%5,%6,%7},{%8,%9},{%0,%1,%2,%3};"            \
                 : "+f"((d)[0]), "+f"((d)[1]), "+f"((d)[2]), "+f"((d)[3])        \
                 : "r"(a0), "r"(a1), "r"(a2), "r"(a3), "r"(b0), "r"(b1))

// ---------------- setup: probe dtype + zero scratch + split weights + x->fp16 ----
static __device__ __forceinline__ void split1h(float v, unsigned short& h, unsigned short& l) {
    __half hv = __float2half_rn(v);
    h = __half_as_ushort(hv);
    l = __half_as_ushort(__float2half_rn(v - __half2float(hv)));
}
__global__ void setup_k(const float* __restrict__ x, const int* __restrict__ ei32,
                        const float* __restrict__ W1l, const float* __restrict__ W1r,
                        const float* __restrict__ W2l, const float* __restrict__ W2r) {
    int i = blockIdx.x * blockDim.x + threadIdx.x; // NN*32 threads
    if (blockIdx.x == 0 && threadIdx.x < 32) {     // edge dtype probe (one warp)
        int lane = threadIdx.x;
        int bad = 0;
#pragma unroll
        for (int q = 0; q < 4; q++)
            if (ei32[2 * (lane + 32 * q) + 1] != 0) bad = 1;
        bad = __any_sync(0xffffffffu, bad);
        if (lane == 0) g_is64 = bad ? 0 : 1;
    }
    if (i < NN) { g_deg[i] = 0; g_cursor[i] = 0; }
    if (i < 128 * 256) { // w1: n = i/256, k = i%256
        int n = i >> 8, k = i & 255;
        float v = (k < 128) ? W1l[k * 128 + n] : W1r[(k - 128) * 128 + n];
        split1h(v, g_w1h[i], g_w1lo[i]);
    }
    if (i < 80 * 128) { // w2: n = i/128, k = i%128
        int n = i >> 7, k = i & 127;
        float v = (n < 40) ? W2l[k * 40 + n] : W2r[k * 40 + (n - 40)];
        split1h(v, g_w2h[i], g_w2lo[i]);
    }
    if (i < NN * 32) { // x -> fp16, 4 elems per thread
        float4 v = ((const float4*)x)[i];
        __half2 h0 = __floats2half2_rn(v.x, v.y);
        __half2 h1 = __floats2half2_rn(v.z, v.w);
        uint2 u;
        u.x = *(uint32_t*)&h0;
        u.y = *(uint32_t*)&h1;
        *(uint2*)(g_xh + (size_t)i * 4) = u;
    }
}

// ---------------- edge convert + degree histogram ----------------
__global__ void convert_k(const void* __restrict__ ei) {
    int e = blockIdx.x * blockDim.x + threadIdx.x;
    if (e >= NE) return;
    int src, dst;
    if (g_is64) {
        src = (int)((const long long*)ei)[e];
        dst = (int)((const long long*)ei)[(long long)NE + e];
    } else {
        src = ((const int*)ei)[e];
        dst = ((const int*)ei)[NE + e];
    }
    g_src[e] = src;
    g_dst[e] = dst;
    atomicAdd(&g_deg[dst], 1);
}

// ---------------- prefix scan ----------------
__global__ __launch_bounds__(1024) void scan1_k() {
    __shared__ int s[1024];
    int t = threadIdx.x;
    int i = blockIdx.x * 1024 + t;
    int v = (i < NN) ? g_deg[i] : 0;
    s[t] = v;
    __syncthreads();
#pragma unroll
    for (int off = 1; off < 1024; off <<= 1) {
        int a = (t >= off) ? s[t - off] : 0;
        __syncthreads();
        s[t] += a;
        __syncthreads();
    }
    if (i < NN) g_scan[i] = s[t];
    if (t == 1023) g_bsum[blockIdx.x] = s[t];
}
__global__ void scan2_k() {
    __shared__ int s[128];
    int t = threadIdx.x;
    s[t] = (t < NB) ? g_bsum[t] : 0;
    __syncthreads();
#pragma unroll
    for (int off = 1; off < 128; off <<= 1) {
        int a = (t >= off) ? s[t - off] : 0;
        __syncthreads();
        s[t] += a;
        __syncthreads();
    }
    if (t < NB) g_bsum[t] = s[t];
}
__global__ void scan3_k() {
    int i = blockIdx.x * blockDim.x + threadIdx.x;
    if (i >= NN) return;
    int b = i >> 10;
    int base = (b > 0) ? g_bsum[b - 1] : 0;
    g_rowstart[i] = base + g_scan[i] - g_deg[i];
}

// ---------------- CSR fill ----------------
__global__ void fill_k() {
    int e = blockIdx.x * blockDim.x + threadIdx.x;
    if (e >= NE) return;
    int d = g_dst[e];
    int pos = g_rowstart[d] + atomicAdd(&g_cursor[d], 1);
    g_csr[pos] = g_src[e];
}

// ---------------- layer-1 gather-mean from fp16 x -> fp16 out (unroll 4) ----------
__global__ void agg1_k() {
    int gt = blockIdx.x * blockDim.x + threadIdx.x;
    int n = gt >> 5;
    int lane = gt & 31;
    if (n >= NN) return;
    int start = g_rowstart[n];
    int deg = g_deg[n];
    float4 acc = make_float4(0.f, 0.f, 0.f, 0.f);
    int i = 0;
    for (; i + 3 < deg; i += 4) {
        int s0 = __ldg(g_csr + start + i);
        int s1 = __ldg(g_csr + start + i + 1);
        int s2 = __ldg(g_csr + start + i + 2);
        int s3 = __ldg(g_csr + start + i + 3);
        uint2 r0 = ((const uint2*)(g_xh + (size_t)s0 * 128))[lane];
        uint2 r1 = ((const uint2*)(g_xh + (size_t)s1 * 128))[lane];
        uint2 r2 = ((const uint2*)(g_xh + (size_t)s2 * 128))[lane];
        uint2 r3 = ((const uint2*)(g_xh + (size_t)s3 * 128))[lane];
        float2 a0 = __half22float2(*(__half2*)&r0.x), b0 = __half22float2(*(__half2*)&r0.y);
        float2 a1 = __half22float2(*(__half2*)&r1.x), b1 = __half22float2(*(__half2*)&r1.y);
        float2 a2 = __half22float2(*(__half2*)&r2.x), b2 = __half22float2(*(__half2*)&r2.y);
        float2 a3 = __half22float2(*(__half2*)&r3.x), b3 = __half22float2(*(__half2*)&r3.y);
        acc.x += (a0.x + a1.x) + (a2.x + a3.x);
        acc.y += (a0.y + a1.y) + (a2.y + a3.y);
        acc.z += (b0.x + b1.x) + (b2.x + b3.x);
        acc.w += (b0.y + b1.y) + (b2.y + b3.y);
    }
    for (; i < deg; i++) {
        int s0 = __ldg(g_csr + start + i);
        uint2 r0 = ((const uint2*)(g_xh + (size_t)s0 * 128))[lane];
        float2 a0 = __half22float2(*(__half2*)&r0.x), b0 = __half22float2(*(__half2*)&r0.y);
        acc.x += a0.x; acc.y += a0.y; acc.z += b0.x; acc.w += b0.y;
    }
    float inv = 1.0f / fmaxf((float)deg, 1.0f);
    __half2 o0 = __floats2half2_rn(acc.x * inv, acc.y * inv);
    __half2 o1 = __floats2half2_rn(acc.z * inv, acc.w * inv);
    uint2 u;
    u.x = *(uint32_t*)&o0;
    u.y = *(uint32_t*)&o1;
    ((uint2*)(g_a1h + (size_t)n * 128))[lane] = u;
}

// ---------------- fp16-A / fp16-hi-lo-B mma.sync GEMM (2 MMAs per tile) --------
// C[M,N] = [A0 | A1](M x KT fp16, split at col 128, both lda=128) @ B(KT x N),
// B = [N][KT] fp16 hi/lo. D += A*Bh + A*Bl (fp32 accum).
// Outputs: optional fp32 C (stride N), fp16 Ch for cols < HCOLS (stride HST).
template <int N, int KT, bool RELU, bool WF32, int HCOLS, int HST>
__global__ __launch_bounds__(256) void gemm_mma(
    int M, const __half* __restrict__ A0, const __half* __restrict__ A1,
    const unsigned short* __restrict__ Bh, const unsigned short* __restrict__ Bl,
    const float* __restrict__ bias, float* __restrict__ C, __half* __restrict__ Ch) {
    constexpr int NT8 = N / 8;
    constexpr int KC = KT / 32;
    constexpr int ST = 40;
    __shared__ unsigned short sA[128 * ST];
    __shared__ unsigned short sBh[N * ST], sBl[N * ST];

    const int tid = threadIdx.x;
    const int wid = tid >> 5, lane = tid & 31;
    const int rowBase = blockIdx.x * 128;

    float acc[NT8][4];
#pragma unroll
    for (int t = 0; t < NT8; t++)
#pragma unroll
        for (int q = 0; q < 4; q++) acc[t][q] = 0.f;

    const int arow = tid >> 1;
    const int ach = (tid & 1) * 16;
    const int gr_a = rowBase + arow;
    const bool a_ok = (gr_a < M);

    for (int c = 0; c < KC; c++) {
        const int gk = c * 32;
        // ---- A chunk: straight fp16 copy (no conversion) ----
        const __half* Ap = (gk < 128) ? (A0 + (size_t)gr_a * 128 + gk + ach)
                                      : (A1 + (size_t)gr_a * 128 + (gk - 128) + ach);
#pragma unroll
        for (int i = 0; i < 2; i++) {
            uint4 v = a_ok ? *(const uint4*)(Ap + i * 8) : make_uint4(0, 0, 0, 0);
            *(uint4*)&sA[arow * ST + ach + i * 8] = v;
        }
        // ---- B chunk: [N][32] fp16 hi/lo straight copy ----
        for (int idx = tid; idx < N * 4; idx += 256) {
            int n = idx >> 2, q = idx & 3;
            *(uint4*)&sBh[n * ST + q * 8] = *(const uint4*)(Bh + (size_t)n * KT + gk + q * 8);
            *(uint4*)&sBl[n * ST + q * 8] = *(const uint4*)(Bl + (size_t)n * KT + gk + q * 8);
        }
        __syncthreads();
#pragma unroll
        for (int ks = 0; ks < 2; ks++) {
            const int kb = ks * 16;
            const int am = wid * 16 + (lane & 7) + ((lane >> 3) & 1) * 8;
            const int ak = kb + (lane >> 4) * 8;
            uint32_t a0, a1, a2, a3;
            {
                uint32_t addr = s2u(&sA[am * ST + ak]);
                LDMX4(a0, a1, a2, a3, addr);
            }
            const int bn = (lane & 7) + (lane >> 4) * 8;
            const int bk = kb + ((lane >> 3) & 1) * 8;
#pragma unroll
            for (int p = 0; p < NT8 / 2; p++) {
                uint32_t bh0, bh1, bh2, bh3, bl0, bl1, bl2, bl3;
                uint32_t addr = s2u(&sBh[(p * 16 + bn) * ST + bk]);
                LDMX4(bh0, bh1, bh2, bh3, addr);
                addr = s2u(&sBl[(p * 16 + bn) * ST + bk]);
                LDMX4(bl0, bl1, bl2, bl3, addr);
                MMAF16(acc[2 * p + 0], a0, a1, a2, a3, bh0, bh1);
                MMAF16(acc[2 * p + 0], a0, a1, a2, a3, bl0, bl1);
                MMAF16(acc[2 * p + 1], a0, a1, a2, a3, bh2, bh3);
                MMAF16(acc[2 * p + 1], a0, a1, a2, a3, bl2, bl3);
            }
        }
        __syncthreads();
    }
    // ---- epilogue ----
    const int r0 = rowBase + wid * 16 + (lane >> 2);
    const int col0 = (lane & 3) * 2;
#pragma unroll
    for (int t = 0; t < NT8; t++) {
        int col = t * 8 + col0;
        float2 v0 = make_float2(acc[t][0], acc[t][1]);
        float2 v1 = make_float2(acc[t][2], acc[t][3]);
        if (RELU) {
            float b0v = __ldg(bias + col), b1v = __ldg(bias + col + 1);
            v0.x = fmaxf(v0.x + b0v, 0.f); v0.y = fmaxf(v0.y + b1v, 0.f);
            v1.x = fmaxf(v1.x + b0v, 0.f); v1.y = fmaxf(v1.y + b1v, 0.f);
        }
        if (r0 < M) {
            if (WF32) *(float2*)(C + (size_t)r0 * N + col) = v0;
            if (col < HCOLS) {
                __half2 hh = __floats2half2_rn(v0.x, v0.y);
                *(uint32_t*)(Ch + (size_t)r0 * HST + col) = *(uint32_t*)&hh;
            }
        }
        if (r0 + 8 < M) {
            if (WF32) *(float2*)(C + (size_t)(r0 + 8) * N + col) = v1;
            if (col < HCOLS) {
                __half2 hh = __floats2half2_rn(v1.x, v1.y);
                *(uint32_t*)(Ch + (size_t)(r0 + 8) * HST + col) = *(uint32_t*)&hh;
            }
        }
    }
}

// ---------------- fused layer-2 gather-mean (fp16) + root + bias + log_softmax ----
__global__ void final_k(const float* __restrict__ b2, float* __restrict__ out) {
    int gt = blockIdx.x * blockDim.x + threadIdx.x;
    int n = gt >> 5;
    int lane = gt & 31;
    if (n >= NN) return;
    int start = g_rowstart[n];
    int deg = g_deg[n];
    int c = lane * 2;
    float2 acc = make_float2(0.f, 0.f);
    if (lane < 20) {
        int i = 0;
        for (; i + 1 < deg; i += 2) {
            int s0 = __ldg(g_csr + start + i);
            int s1 = __ldg(g_csr + start + i + 1);
            uint32_t r0 = *(const uint32_t*)(g_trh + (size_t)s0 * 40 + c);
            uint32_t r1 = *(const uint32_t*)(g_trh + (size_t)s1 * 40 + c);
            float2 v0 = __half22float2(*(__half2*)&r0);
            float2 v1 = __half22float2(*(__half2*)&r1);
            acc.x += v0.x + v1.x;
            acc.y += v0.y + v1.y;
        }
        if (i < deg) {
            int s0 = __ldg(g_csr + start + i);
            uint32_t r0 = *(const uint32_t*)(g_trh + (size_t)s0 * 40 + c);
            float2 v0 = __half22float2(*(__half2*)&r0);
            acc.x += v0.x;
            acc.y += v0.y;
        }
    }
    float inv = 1.0f / fmaxf((float)deg, 1.0f);
    float e0 = -3.4e38f, e1 = -3.4e38f;
    if (lane < 20) {
        e0 = acc.x * inv + g_tr[(size_t)n * 80 + 40 + c] + b2[c];
        e1 = acc.y * inv + g_tr[(size_t)n * 80 + 41 + c] + b2[c + 1];
    }
    float m = fmaxf(e0, e1);
#pragma unroll
    for (int o = 16; o > 0; o >>= 1) m = fmaxf(m, __shfl_xor_sync(0xffffffffu, m, o));
    float s = (lane < 20) ? (expf(e0 - m) + expf(e1 - m)) : 0.f;
#pragma unroll
    for (int o = 16; o > 0; o >>= 1) s += __shfl_xor_sync(0xffffffffu, s, o);
    float lse = m + logf(s);
    if (lane < 20) {
        float2 o2;
        o2.x = e0 - lse;
        o2.y = e1 - lse;
        *(float2*)(out + (size_t)n * 40 + c) = o2;
    }
}

// ---------------- launch ----------------
extern "C" void kernel_launch(void* const* d_in, const int* in_sizes, int n_in,
                              void* d_out, int out_size) {
    const float* x   = (const float*)d_in[0];
    const void* ei   = d_in[1];
    const float* W1l = (const float*)d_in[2];
    const float* W1r = (const float*)d_in[3];
    const float* b1  = (const float*)d_in[4];
    const float* W2l = (const float*)d_in[5];
    const float* W2r = (const float*)d_in[6];
    const float* b2  = (const float*)d_in[7];
    float* out       = (float*)d_out;

    __half *xh, *a1h, *hh, *trh;
    float* tr;
    unsigned short *w1h, *w1lo, *w2h, *w2lo;
    cudaGetSymbolAddress((void**)&xh, g_xh);
    cudaGetSymbolAddress((void**)&a1h, g_a1h);
    cudaGetSymbolAddress((void**)&hh, g_hh);
    cudaGetSymbolAddress((void**)&tr, g_tr);
    cudaGetSymbolAddress((void**)&trh, g_trh);
    cudaGetSymbolAddress((void**)&w1h, g_w1h);
    cudaGetSymbolAddress((void**)&w1lo, g_w1lo);
    cudaGetSymbolAddress((void**)&w2h, g_w2h);
    cudaGetSymbolAddress((void**)&w2lo, g_w2lo);

    const int mtiles = (NN + 127) / 128; // 782

    setup_k<<<(NN * 32 + 255) / 256, 256>>>(x, (const int*)ei, W1l, W1r, W2l, W2r);
    convert_k<<<(NE + 255) / 256, 256>>>(ei);
    scan1_k<<<NB, 1024>>>();
    scan2_k<<<1, 128>>>();
    scan3_k<<<(NN + 255) / 256, 256>>>();
    fill_k<<<(NE + 255) / 256, 256>>>();
    agg1_k<<<(NN * 32 + 255) / 256, 256>>>();
    // gemm1: h(fp16 only) = relu([agg|x] @ W1 + b1)
    gemm_mma<128, 256, true, false, 128, 128><<<mtiles, 256>>>(
        NN, a1h, xh, w1h, w1lo, b1, nullptr, hh);
    // gemm2: tr(fp32) = h @ [W2l|W2r]; trh(fp16) = tr[:, 0:40]
    gemm_mma<80, 128, false, true, 40, 40><<<mtiles, 256>>>(
        NN, hh, hh, w2h, w2lo, nullptr, tr, trh);
    final_k<<<(NN * 32 + 255) / 256, 256>>>(b2, out);
}

// round 16
// speedup vs baseline: 1.2857x; 1.0259x over previous
#include <cuda_runtime.h>
#include <cuda_fp16.h>
#include <math.h>
#include <stdint.h>

#define NN 100000
#define NE 1600000
#define NB 98  // ceil(NN/1024) scan blocks

// ---------------- scratch (static __device__, no allocation) ----------------
// INVARIANT: g_deg is zero at kernel_launch entry (zero-initialized at module
// load; re-zeroed by final_k at the end of every run). g_cursor is zeroed by
// scan23_k before fill_k uses it.
__device__ __align__(16) __half g_xh[(size_t)NN * 128];   // fp16 copy of x
__device__ __align__(16) __half g_a1h[(size_t)NN * 128];  // layer-1 neighbor means
__device__ __align__(16) __half g_hh[(size_t)NN * 128];   // h = relu(...) (fp16)
__device__ __align__(16) __half g_trh[(size_t)NN * 40];   // h@W2l (gathered part, fp16)
__device__ __align__(16) __half g_trr[(size_t)NN * 40];   // h@W2r (root part, fp16)
// weights pre-transposed to [N][K] (K contiguous), split into fp16 hi/lo
__device__ __align__(16) unsigned short g_w1h[128 * 256];
__device__ __align__(16) unsigned short g_w1lo[128 * 256];
__device__ __align__(16) unsigned short g_w2h[80 * 128];
__device__ __align__(16) unsigned short g_w2lo[80 * 128];
__device__ int g_src[NE];
__device__ int g_dst[NE];
__device__ int g_csr[NE];
__device__ int g_deg[NN];       // zero at entry (see invariant above)
__device__ int g_rowstart[NN];
__device__ int g_cursor[NN];
__device__ int g_scan[NN];
__device__ int g_bsum[NB];

// ---------------- PTX helpers ----------------
static __device__ __forceinline__ uint32_t s2u(const void* p) {
    uint32_t a;
    asm("{ .reg .u64 t; cvta.to.shared.u64 t, %1; cvt.u32.u64 %0, t; }" : "=r"(a) : "l"(p));
    return a;
}
#define LDMX4(r0, r1, r2, r3, addr)                                             \
    asm volatile("ldmatrix.sync.aligned.m8n8.x4.shared.b16 {%0,%1,%2,%3}, [%4];" \
                 : "=r"(r0), "=r"(r1), "=r"(r2), "=r"(r3) : "r"(addr))
#define MMAF16(d, a0, a1, a2, a3, b0, b1)                                        \
    asm volatile("mma.sync.aligned.m16n8k16.row.col.f32.f16.f16.f32 "            \
                 "{%0,%1,%2,%3},{%4,%5,%6,%7},{%8,%9},{%0,%1,%2,%3};"            \
                 : "+f"((d)[0]), "+f"((d)[1]), "+f"((d)[2]), "+f"((d)[3])        \
                 : "r"(a0), "r"(a1), "r"(a2), "r"(a3), "r"(b0), "r"(b1))

// ---------------- fused setup: probe + weights + x->fp16 + edge convert + histogram
static __device__ __forceinline__ void split1h(float v, unsigned short& h, unsigned short& l) {
    __half hv = __float2half_rn(v);
    h = __half_as_ushort(hv);
    l = __half_as_ushort(__float2half_rn(v - __half2float(hv)));
}
__global__ void fused0_k(const float* __restrict__ x, const void* __restrict__ ei,
                         const float* __restrict__ W1l, const float* __restrict__ W1r,
                         const float* __restrict__ W2l, const float* __restrict__ W2r) {
    __shared__ int s_is64;
    const int* ei32 = (const int*)ei;
    if (threadIdx.x < 32) { // per-block probe: no cross-block ordering needed
        int lane = threadIdx.x;
        int bad = 0;
#pragma unroll
        for (int q = 0; q < 4; q++)
            if (ei32[2 * (lane + 32 * q) + 1] != 0) bad = 1;
        bad = __any_sync(0xffffffffu, bad);
        if (lane == 0) s_is64 = bad ? 0 : 1;
    }
    __syncthreads();
    const int is64 = s_is64;
    int i = blockIdx.x * blockDim.x + threadIdx.x; // NN*32 = 3.2M threads
    if (i < 128 * 256) { // w1: n = i/256, k = i%256
        int n = i >> 8, k = i & 255;
        float v = (k < 128) ? W1l[k * 128 + n] : W1r[(k - 128) * 128 + n];
        split1h(v, g_w1h[i], g_w1lo[i]);
    }
    if (i < 80 * 128) { // w2: n = i/128, k = i%128
        int n = i >> 7, k = i & 127;
        float v = (n < 40) ? W2l[k * 40 + n] : W2r[k * 40 + (n - 40)];
        split1h(v, g_w2h[i], g_w2lo[i]);
    }
    if (i < NN * 32) { // x -> fp16, 4 elems per thread
        float4 v = ((const float4*)x)[i];
        __half2 h0 = __floats2half2_rn(v.x, v.y);
        __half2 h1 = __floats2half2_rn(v.z, v.w);
        uint2 u;
        u.x = *(uint32_t*)&h0;
        u.y = *(uint32_t*)&h1;
        *(uint2*)(g_xh + (size_t)i * 4) = u;
    }
    if (i < NE) { // edge convert + degree histogram (g_deg zero at entry)
        int src, dst;
        if (is64) {
            src = (int)((const long long*)ei)[i];
            dst = (int)((const long long*)ei)[(long long)NE + i];
        } else {
            src = ei32[i];
            dst = ei32[NE + i];
        }
        g_src[i] = src;
        g_dst[i] = dst;
        atomicAdd(&g_deg[dst], 1);
    }
}

// ---------------- prefix scan: per-block inclusive ----------------
__global__ __launch_bounds__(1024) void scan1_k() {
    __shared__ int s[1024];
    int t = threadIdx.x;
    int i = blockIdx.x * 1024 + t;
    int v = (i < NN) ? g_deg[i] : 0;
    s[t] = v;
    __syncthreads();
#pragma unroll
    for (int off = 1; off < 1024; off <<= 1) {
        int a = (t >= off) ? s[t - off] : 0;
        __syncthreads();
        s[t] += a;
        __syncthreads();
    }
    if (i < NN) g_scan[i] = s[t];
    if (t == 1023) g_bsum[blockIdx.x] = s[t];
}
// ---------------- merged: bsum scan (per-block, redundant) + rowstart + cursor zero
__global__ void scan23_k() {
    __shared__ int sb[128];
    int t = threadIdx.x; // 256 threads
    if (t < 128) sb[t] = (t < NB) ? g_bsum[t] : 0;
    __syncthreads();
#pragma unroll
    for (int off = 1; off < 128; off <<= 1) {
        int a = (t < 128 && t >= off) ? sb[t - off] : 0;
        __syncthreads();
        if (t < 128) sb[t] += a;
        __syncthreads();
    }
    int i = blockIdx.x * 256 + t;
    if (i < NN) {
        int b = i >> 10;
        int base = (b > 0) ? sb[b - 1] : 0;
        g_rowstart[i] = base + g_scan[i] - g_deg[i]; // exclusive
        g_cursor[i] = 0;
    }
}

// ---------------- CSR fill ----------------
__global__ void fill_k() {
    int e = blockIdx.x * blockDim.x + threadIdx.x;
    if (e >= NE) return;
    int d = g_dst[e];
    int pos = g_rowstart[d] + atomicAdd(&g_cursor[d], 1);
    g_csr[pos] = g_src[e];
}

// ---------------- layer-1 gather-mean from fp16 x -> fp16 out (unroll 4) --------
__global__ void agg1_k() {
    int gt = blockIdx.x * blockDim.x + threadIdx.x;
    int n = gt >> 5;
    int lane = gt & 31;
    if (n >= NN) return;
    int start = g_rowstart[n];
    int deg = g_deg[n];
    float4 acc = make_float4(0.f, 0.f, 0.f, 0.f);
    int i = 0;
    for (; i + 3 < deg; i += 4) {
        int s0 = __ldg(g_csr + start + i);
        int s1 = __ldg(g_csr + start + i + 1);
        int s2 = __ldg(g_csr + start + i + 2);
        int s3 = __ldg(g_csr + start + i + 3);
        uint2 r0 = ((const uint2*)(g_xh + (size_t)s0 * 128))[lane];
        uint2 r1 = ((const uint2*)(g_xh + (size_t)s1 * 128))[lane];
        uint2 r2 = ((const uint2*)(g_xh + (size_t)s2 * 128))[lane];
        uint2 r3 = ((const uint2*)(g_xh + (size_t)s3 * 128))[lane];
        float2 a0 = __half22float2(*(__half2*)&r0.x), b0 = __half22float2(*(__half2*)&r0.y);
        float2 a1 = __half22float2(*(__half2*)&r1.x), b1 = __half22float2(*(__half2*)&r1.y);
        float2 a2 = __half22float2(*(__half2*)&r2.x), b2 = __half22float2(*(__half2*)&r2.y);
        float2 a3 = __half22float2(*(__half2*)&r3.x), b3 = __half22float2(*(__half2*)&r3.y);
        acc.x += (a0.x + a1.x) + (a2.x + a3.x);
        acc.y += (a0.y + a1.y) + (a2.y + a3.y);
        acc.z += (b0.x + b1.x) + (b2.x + b3.x);
        acc.w += (b0.y + b1.y) + (b2.y + b3.y);
    }
    for (; i < deg; i++) {
        int s0 = __ldg(g_csr + start + i);
        uint2 r0 = ((const uint2*)(g_xh + (size_t)s0 * 128))[lane];
        float2 a0 = __half22float2(*(__half2*)&r0.x), b0 = __half22float2(*(__half2*)&r0.y);
        acc.x += a0.x; acc.y += a0.y; acc.z += b0.x; acc.w += b0.y;
    }
    float inv = 1.0f / fmaxf((float)deg, 1.0f);
    __half2 o0 = __floats2half2_rn(acc.x * inv, acc.y * inv);
    __half2 o1 = __floats2half2_rn(acc.z * inv, acc.w * inv);
    uint2 u;
    u.x = *(uint32_t*)&o0;
    u.y = *(uint32_t*)&o1;
    ((uint2*)(g_a1h + (size_t)n * 128))[lane] = u;
}

// ---------------- fp16-A / fp16-hi-lo-B mma.sync GEMM (2 MMAs per tile) --------
// C[M,N] = [A0 | A1](M x KT fp16, split at col 128) @ B(KT x N), B = [N][KT]
// fp16 hi/lo. D += A*Bh + A*Bl (fp32 accum).
// MODE 0: store all N cols fp16 to Ch (stride 128).
// MODE 1: cols<40 -> Ch (stride 40), cols>=40 -> Cr (stride 40, col-40).
template <int N, int KT, bool RELU, int MODE>
__global__ __launch_bounds__(256) void gemm_mma(
    int M, const __half* __restrict__ A0, const __half* __restrict__ A1,
    const unsigned short* __restrict__ Bh, const unsigned short* __restrict__ Bl,
    const float* __restrict__ bias, __half* __restrict__ Ch, __half* __restrict__ Cr) {
    constexpr int NT8 = N / 8;
    constexpr int KC = KT / 32;
    constexpr int ST = 40;
    __shared__ unsigned short sA[128 * ST];
    __shared__ unsigned short sBh[N * ST], sBl[N * ST];

    const int tid = threadIdx.x;
    const int wid = tid >> 5, lane = tid & 31;
    const int rowBase = blockIdx.x * 128;

    float acc[NT8][4];
#pragma unroll
    for (int t = 0; t < NT8; t++)
#pragma unroll
        for (int q = 0; q < 4; q++) acc[t][q] = 0.f;

    const int arow = tid >> 1;
    const int ach = (tid & 1) * 16;
    const int gr_a = rowBase + arow;
    const bool a_ok = (gr_a < M);

    for (int c = 0; c < KC; c++) {
        const int gk = c * 32;
        const __half* Ap = (gk < 128) ? (A0 + (size_t)gr_a * 128 + gk + ach)
                                      : (A1 + (size_t)gr_a * 128 + (gk - 128) + ach);
#pragma unroll
        for (int i = 0; i < 2; i++) {
            uint4 v = a_ok ? *(const uint4*)(Ap + i * 8) : make_uint4(0, 0, 0, 0);
            *(uint4*)&sA[arow * ST + ach + i * 8] = v;
        }
        for (int idx = tid; idx < N * 4; idx += 256) {
            int n = idx >> 2, q = idx & 3;
            *(uint4*)&sBh[n * ST + q * 8] = *(const uint4*)(Bh + (size_t)n * KT + gk + q * 8);
            *(uint4*)&sBl[n * ST + q * 8] = *(const uint4*)(Bl + (size_t)n * KT + gk + q * 8);
        }
        __syncthreads();
#pragma unroll
        for (int ks = 0; ks < 2; ks++) {
            const int kb = ks * 16;
            const int am = wid * 16 + (lane & 7) + ((lane >> 3) & 1) * 8;
            const int ak = kb + (lane >> 4) * 8;
            uint32_t a0, a1, a2, a3;
            {
                uint32_t addr = s2u(&sA[am * ST + ak]);
                LDMX4(a0, a1, a2, a3, addr);
            }
            const int bn = (lane & 7) + (lane >> 4) * 8;
            const int bk = kb + ((lane >> 3) & 1) * 8;
#pragma unroll
            for (int p = 0; p < NT8 / 2; p++) {
                uint32_t bh0, bh1, bh2, bh3, bl0, bl1, bl2, bl3;
                uint32_t addr = s2u(&sBh[(p * 16 + bn) * ST + bk]);
                LDMX4(bh0, bh1, bh2, bh3, addr);
                addr = s2u(&sBl[(p * 16 + bn) * ST + bk]);
                LDMX4(bl0, bl1, bl2, bl3, addr);
                MMAF16(acc[2 * p + 0], a0, a1, a2, a3, bh0, bh1);
                MMAF16(acc[2 * p + 0], a0, a1, a2, a3, bl0, bl1);
                MMAF16(acc[2 * p + 1], a0, a1, a2, a3, bh2, bh3);
                MMAF16(acc[2 * p + 1], a0, a1, a2, a3, bl2, bl3);
            }
        }
        __syncthreads();
    }
    // ---- epilogue (all-fp16 outputs) ----
    const int r0 = rowBase + wid * 16 + (lane >> 2);
    const int col0 = (lane & 3) * 2;
#pragma unroll
    for (int t = 0; t < NT8; t++) {
        int col = t * 8 + col0;
        float2 v0 = make_float2(acc[t][0], acc[t][1]);
        float2 v1 = make_float2(acc[t][2], acc[t][3]);
        if (RELU) {
            float b0v = __ldg(bias + col), b1v = __ldg(bias + col + 1);
            v0.x = fmaxf(v0.x + b0v, 0.f); v0.y = fmaxf(v0.y + b1v, 0.f);
            v1.x = fmaxf(v1.x + b0v, 0.f); v1.y = fmaxf(v1.y + b1v, 0.f);
        }
        __half2 h0 = __floats2half2_rn(v0.x, v0.y);
        __half2 h1 = __floats2half2_rn(v1.x, v1.y);
        if (MODE == 0) {
            if (r0 < M)     *(uint32_t*)(Ch + (size_t)r0 * 128 + col) = *(uint32_t*)&h0;
            if (r0 + 8 < M) *(uint32_t*)(Ch + (size_t)(r0 + 8) * 128 + col) = *(uint32_t*)&h1;
        } else {
            __half* P0 = (col < 40) ? (Ch + (size_t)r0 * 40 + col)
                                    : (Cr + (size_t)r0 * 40 + col - 40);
            __half* P1 = (col < 40) ? (Ch + (size_t)(r0 + 8) * 40 + col)
                                    : (Cr + (size_t)(r0 + 8) * 40 + col - 40);
            if (r0 < M)     *(uint32_t*)P0 = *(uint32_t*)&h0;
            if (r0 + 8 < M) *(uint32_t*)P1 = *(uint32_t*)&h1;
        }
    }
}

// ---------------- fused layer-2 gather-mean + root + bias + log_softmax --------
// Also re-zeroes g_deg for the next run (invariant).
__global__ void final_k(const float* __restrict__ b2, float* __restrict__ out) {
    int gt = blockIdx.x * blockDim.x + threadIdx.x;
    int n = gt >> 5;
    int lane = gt & 31;
    if (n >= NN) return;
    int start = g_rowstart[n];
    int deg = g_deg[n];
    int c = lane * 2;
    float2 acc = make_float2(0.f, 0.f);
    if (lane < 20) {
        int i = 0;
        for (; i + 1 < deg; i += 2) {
            int s0 = __ldg(g_csr + start + i);
            int s1 = __ldg(g_csr + start + i + 1);
            uint32_t r0 = *(const uint32_t*)(g_trh + (size_t)s0 * 40 + c);
            uint32_t r1 = *(const uint32_t*)(g_trh + (size_t)s1 * 40 + c);
            float2 v0 = __half22float2(*(__half2*)&r0);
            float2 v1 = __half22float2(*(__half2*)&r1);
            acc.x += v0.x + v1.x;
            acc.y += v0.y + v1.y;
        }
        if (i < deg) {
            int s0 = __ldg(g_csr + start + i);
            uint32_t r0 = *(const uint32_t*)(g_trh + (size_t)s0 * 40 + c);
            float2 v0 = __half22float2(*(__half2*)&r0);
            acc.x += v0.x;
            acc.y += v0.y;
        }
    }
    if (lane == 0) g_deg[n] = 0; // restore invariant for next run
    float inv = 1.0f / fmaxf((float)deg, 1.0f);
    float e0 = -3.4e38f, e1 = -3.4e38f;
    if (lane < 20) {
        uint32_t rr = *(const uint32_t*)(g_trr + (size_t)n * 40 + c);
        float2 root = __half22float2(*(__half2*)&rr);
        e0 = acc.x * inv + root.x + b2[c];
        e1 = acc.y * inv + root.y + b2[c + 1];
    }
    float m = fmaxf(e0, e1);
#pragma unroll
    for (int o = 16; o > 0; o >>= 1) m = fmaxf(m, __shfl_xor_sync(0xffffffffu, m, o));
    float s = (lane < 20) ? (expf(e0 - m) + expf(e1 - m)) : 0.f;
#pragma unroll
    for (int o = 16; o > 0; o >>= 1) s += __shfl_xor_sync(0xffffffffu, s, o);
    float lse = m + logf(s);
    if (lane < 20) {
        float2 o2;
        o2.x = e0 - lse;
        o2.y = e1 - lse;
        *(float2*)(out + (size_t)n * 40 + c) = o2;
    }
}

// ---------------- launch ----------------
extern "C" void kernel_launch(void* const* d_in, const int* in_sizes, int n_in,
                              void* d_out, int out_size) {
    const float* x   = (const float*)d_in[0];
    const void* ei   = d_in[1];
    const float* W1l = (const float*)d_in[2];
    const float* W1r = (const float*)d_in[3];
    const float* b1  = (const float*)d_in[4];
    const float* W2l = (const float*)d_in[5];
    const float* W2r = (const float*)d_in[6];
    const float* b2  = (const float*)d_in[7];
    float* out       = (float*)d_out;

    __half *xh, *a1h, *hh, *trh, *trr;
    unsigned short *w1h, *w1lo, *w2h, *w2lo;
    cudaGetSymbolAddress((void**)&xh, g_xh);
    cudaGetSymbolAddress((void**)&a1h, g_a1h);
    cudaGetSymbolAddress((void**)&hh, g_hh);
    cudaGetSymbolAddress((void**)&trh, g_trh);
    cudaGetSymbolAddress((void**)&trr, g_trr);
    cudaGetSymbolAddress((void**)&w1h, g_w1h);
    cudaGetSymbolAddress((void**)&w1lo, g_w1lo);
    cudaGetSymbolAddress((void**)&w2h, g_w2h);
    cudaGetSymbolAddress((void**)&w2lo, g_w2lo);

    const int mtiles = (NN + 127) / 128; // 782

    fused0_k<<<(NN * 32 + 255) / 256, 256>>>(x, ei, W1l, W1r, W2l, W2r);
    scan1_k<<<NB, 1024>>>();
    scan23_k<<<(NN + 255) / 256, 256>>>();
    fill_k<<<(NE + 255) / 256, 256>>>();
    agg1_k<<<(NN * 32 + 255) / 256, 256>>>();
    gemm_mma<128, 256, true, 0><<<mtiles, 256>>>(NN, a1h, xh, w1h, w1lo, b1, hh, nullptr);
    gemm_mma<80, 128, false, 1><<<mtiles, 256>>>(NN, hh, hh, w2h, w2lo, nullptr, trh, trr);
    final_k<<<(NN * 32 + 255) / 256, 256>>>(b2, out);
}

// round 17
// speedup vs baseline: 1.2897x; 1.0031x over previous
#include <cuda_runtime.h>
#include <cuda_fp16.h>
#include <math.h>
#include <stdint.h>

#define NN 100000
#define NE 1600000
#define NB 98  // ceil(NN/1024) scan blocks

// ---------------- scratch (static __device__, no allocation) ----------------
// INVARIANT: g_deg is zero at kernel_launch entry (zero-initialized at module
// load; re-zeroed by final_k at the end of every run). g_cursor is zeroed by
// scan23_k before fill_k uses it.
__device__ __align__(16) __half g_xh[(size_t)NN * 128];   // fp16 copy of x
__device__ __align__(16) __half g_a1h[(size_t)NN * 128];  // layer-1 neighbor means
__device__ __align__(16) __half g_hh[(size_t)NN * 128];   // h = relu(...) (fp16)
__device__ __align__(16) __half g_trh[(size_t)NN * 40];   // h@W2l (gathered part, fp16)
__device__ __align__(16) __half g_trr[(size_t)NN * 40];   // h@W2r (root part, fp16)
// weights pre-transposed to [N][K] (K contiguous), split into fp16 hi/lo
__device__ __align__(16) unsigned short g_w1h[128 * 256];
__device__ __align__(16) unsigned short g_w1lo[128 * 256];
__device__ __align__(16) unsigned short g_w2h[80 * 128];
__device__ __align__(16) unsigned short g_w2lo[80 * 128];
__device__ int g_csr[NE];
__device__ int g_deg[NN];       // zero at entry (see invariant above)
__device__ int g_rowstart[NN];
__device__ int g_cursor[NN];
__device__ int g_scan[NN];
__device__ int g_bsum[NB];
__device__ int g_is64;          // written by fused0_k block 0; read by fill_k

// ---------------- PTX helpers ----------------
static __device__ __forceinline__ uint32_t s2u(const void* p) {
    uint32_t a;
    asm("{ .reg .u64 t; cvta.to.shared.u64 t, %1; cvt.u32.u64 %0, t; }" : "=r"(a) : "l"(p));
    return a;
}
#define LDMX4(r0, r1, r2, r3, addr)                                             \
    asm volatile("ldmatrix.sync.aligned.m8n8.x4.shared.b16 {%0,%1,%2,%3}, [%4];" \
                 : "=r"(r0), "=r"(r1), "=r"(r2), "=r"(r3) : "r"(addr))
#define MMAF16(d, a0, a1, a2, a3, b0, b1)                                        \
    asm volatile("mma.sync.aligned.m16n8k16.row.col.f32.f16.f16.f32 "            \
                 "{%0,%1,%2,%3},{%4,%5,%6,%7},{%8,%9},{%0,%1,%2,%3};"            \
                 : "+f"((d)[0]), "+f"((d)[1]), "+f"((d)[2]), "+f"((d)[3])        \
                 : "r"(a0), "r"(a1), "r"(a2), "r"(a3), "r"(b0), "r"(b1))

// ---------------- fused setup: probe + weights + x->fp16 + degree histogram ----
static __device__ __forceinline__ void split1h(float v, unsigned short& h, unsigned short& l) {
    __half hv = __float2half_rn(v);
    h = __half_as_ushort(hv);
    l = __half_as_ushort(__float2half_rn(v - __half2float(hv)));
}
__global__ void fused0_k(const float* __restrict__ x, const void* __restrict__ ei,
                         const float* __restrict__ W1l, const float* __restrict__ W1r,
                         const float* __restrict__ W2l, const float* __restrict__ W2r) {
    __shared__ int s_is64;
    const int* ei32 = (const int*)ei;
    if (threadIdx.x < 32) { // per-block probe: no cross-block ordering needed
        int lane = threadIdx.x;
        int bad = 0;
#pragma unroll
        for (int q = 0; q < 4; q++)
            if (ei32[2 * (lane + 32 * q) + 1] != 0) bad = 1;
        bad = __any_sync(0xffffffffu, bad);
        if (lane == 0) {
            s_is64 = bad ? 0 : 1;
            if (blockIdx.x == 0) g_is64 = s_is64; // for fill_k (runs later)
        }
    }
    __syncthreads();
    const int is64 = s_is64;
    int i = blockIdx.x * blockDim.x + threadIdx.x; // NN*32 = 3.2M threads
    if (i < 128 * 256) { // w1: n = i/256, k = i%256
        int n = i >> 8, k = i & 255;
        float v = (k < 128) ? W1l[k * 128 + n] : W1r[(k - 128) * 128 + n];
        split1h(v, g_w1h[i], g_w1lo[i]);
    }
    if (i < 80 * 128) { // w2: n = i/128, k = i%128
        int n = i >> 7, k = i & 127;
        float v = (n < 40) ? W2l[k * 40 + n] : W2r[k * 40 + (n - 40)];
        split1h(v, g_w2h[i], g_w2lo[i]);
    }
    if (i < NN * 32) { // x -> fp16, 4 elems per thread
        float4 v = ((const float4*)x)[i];
        __half2 h0 = __floats2half2_rn(v.x, v.y);
        __half2 h1 = __floats2half2_rn(v.z, v.w);
        uint2 u;
        u.x = *(uint32_t*)&h0;
        u.y = *(uint32_t*)&h1;
        *(uint2*)(g_xh + (size_t)i * 4) = u;
    }
    if (i < NE) { // degree histogram (g_deg zero at entry)
        int dst = is64 ? (int)((const long long*)ei)[(long long)NE + i] : ei32[NE + i];
        atomicAdd(&g_deg[dst], 1);
    }
}

// ---------------- prefix scan: per-block inclusive ----------------
__global__ __launch_bounds__(1024) void scan1_k() {
    __shared__ int s[1024];
    int t = threadIdx.x;
    int i = blockIdx.x * 1024 + t;
    int v = (i < NN) ? g_deg[i] : 0;
    s[t] = v;
    __syncthreads();
#pragma unroll
    for (int off = 1; off < 1024; off <<= 1) {
        int a = (t >= off) ? s[t - off] : 0;
        __syncthreads();
        s[t] += a;
        __syncthreads();
    }
    if (i < NN) g_scan[i] = s[t];
    if (t == 1023) g_bsum[blockIdx.x] = s[t];
}
// ---------------- merged: bsum scan (per-block, redundant) + rowstart + cursor zero
__global__ void scan23_k() {
    __shared__ int sb[128];
    int t = threadIdx.x; // 256 threads
    if (t < 128) sb[t] = (t < NB) ? g_bsum[t] : 0;
    __syncthreads();
#pragma unroll
    for (int off = 1; off < 128; off <<= 1) {
        int a = (t < 128 && t >= off) ? sb[t - off] : 0;
        __syncthreads();
        if (t < 128) sb[t] += a;
        __syncthreads();
    }
    int i = blockIdx.x * 256 + t;
    if (i < NN) {
        int b = i >> 10;
        int base = (b > 0) ? sb[b - 1] : 0;
        g_rowstart[i] = base + g_scan[i] - g_deg[i]; // exclusive
        g_cursor[i] = 0;
    }
}

// ---------------- CSR fill (decodes ei directly) ----------------
__global__ void fill_k(const void* __restrict__ ei) {
    int e = blockIdx.x * blockDim.x + threadIdx.x;
    if (e >= NE) return;
    int src, dst;
    if (g_is64) {
        src = (int)((const long long*)ei)[e];
        dst = (int)((const long long*)ei)[(long long)NE + e];
    } else {
        src = ((const int*)ei)[e];
        dst = ((const int*)ei)[NE + e];
    }
    int pos = g_rowstart[dst] + atomicAdd(&g_cursor[dst], 1);
    g_csr[pos] = src;
}

// ---------------- layer-1 gather-mean: half-warp x uint4 scheme ----------------
// lanes 0-15 process even-index neighbors, lanes 16-31 odd-index; each lane
// loads uint4 = 8 halves (channels 8*hl .. 8*hl+7). Combine via shfl_xor(16).
__global__ void agg1_k() {
    int gt = blockIdx.x * blockDim.x + threadIdx.x;
    int n = gt >> 5;
    int lane = gt & 31;
    if (n >= NN) return;
    int start = g_rowstart[n];
    int deg = g_deg[n];
    const int half = lane >> 4;  // 0 or 1
    const int hl = lane & 15;    // channel group
    float acc[8];
#pragma unroll
    for (int q = 0; q < 8; q++) acc[q] = 0.f;

    int i = half;
    for (; i + 2 < deg; i += 4) { // this half-warp: neighbors i and i+2
        int s0 = __ldg(g_csr + start + i);
        int s1 = __ldg(g_csr + start + i + 2);
        uint4 r0 = ((const uint4*)(g_xh + (size_t)s0 * 128))[hl];
        uint4 r1 = ((const uint4*)(g_xh + (size_t)s1 * 128))[hl];
        float2 f0 = __half22float2(*(__half2*)&r0.x), g0 = __half22float2(*(__half2*)&r1.x);
        float2 f1 = __half22float2(*(__half2*)&r0.y), g1 = __half22float2(*(__half2*)&r1.y);
        float2 f2 = __half22float2(*(__half2*)&r0.z), g2 = __half22float2(*(__half2*)&r1.z);
        float2 f3 = __half22float2(*(__half2*)&r0.w), g3 = __half22float2(*(__half2*)&r1.w);
        acc[0] += f0.x + g0.x; acc[1] += f0.y + g0.y;
        acc[2] += f1.x + g1.x; acc[3] += f1.y + g1.y;
        acc[4] += f2.x + g2.x; acc[5] += f2.y + g2.y;
        acc[6] += f3.x + g3.x; acc[7] += f3.y + g3.y;
    }
    if (i < deg) {
        int s0 = __ldg(g_csr + start + i);
        uint4 r0 = ((const uint4*)(g_xh + (size_t)s0 * 128))[hl];
        float2 f0 = __half22float2(*(__half2*)&r0.x);
        float2 f1 = __half22float2(*(__half2*)&r0.y);
        float2 f2 = __half22float2(*(__half2*)&r0.z);
        float2 f3 = __half22float2(*(__half2*)&r0.w);
        acc[0] += f0.x; acc[1] += f0.y; acc[2] += f1.x; acc[3] += f1.y;
        acc[4] += f2.x; acc[5] += f2.y; acc[6] += f3.x; acc[7] += f3.y;
    }
    // combine the two half-warps
#pragma unroll
    for (int q = 0; q < 8; q++)
        acc[q] += __shfl_xor_sync(0xffffffffu, acc[q], 16);
    if (half == 0) {
        float inv = 1.0f / fmaxf((float)deg, 1.0f);
        __half2 o0 = __floats2half2_rn(acc[0] * inv, acc[1] * inv);
        __half2 o1 = __floats2half2_rn(acc[2] * inv, acc[3] * inv);
        __half2 o2 = __floats2half2_rn(acc[4] * inv, acc[5] * inv);
        __half2 o3 = __floats2half2_rn(acc[6] * inv, acc[7] * inv);
        uint4 u;
        u.x = *(uint32_t*)&o0;
        u.y = *(uint32_t*)&o1;
        u.z = *(uint32_t*)&o2;
        u.w = *(uint32_t*)&o3;
        ((uint4*)(g_a1h + (size_t)n * 128))[hl] = u;
    }
}

// ---------------- fp16-A / fp16-hi-lo-B mma.sync GEMM (2 MMAs per tile) --------
// C[M,N] = [A0 | A1](M x KT fp16, split at col 128) @ B(KT x N), B = [N][KT]
// fp16 hi/lo. D += A*Bh + A*Bl (fp32 accum).
// MODE 0: store all N cols fp16 to Ch (stride 128).
// MODE 1: cols<40 -> Ch (stride 40), cols>=40 -> Cr (stride 40, col-40).
template <int N, int KT, bool RELU, int MODE>
__global__ __launch_bounds__(256) void gemm_mma(
    int M, const __half* __restrict__ A0, const __half* __restrict__ A1,
    const unsigned short* __restrict__ Bh, const unsigned short* __restrict__ Bl,
    const float* __restrict__ bias, __half* __restrict__ Ch, __half* __restrict__ Cr) {
    constexpr int NT8 = N / 8;
    constexpr int KC = KT / 32;
    constexpr int ST = 40;
    __shared__ unsigned short sA[128 * ST];
    __shared__ unsigned short sBh[N * ST], sBl[N * ST];

    const int tid = threadIdx.x;
    const int wid = tid >> 5, lane = tid & 31;
    const int rowBase = blockIdx.x * 128;

    float acc[NT8][4];
#pragma unroll
    for (int t = 0; t < NT8; t++)
#pragma unroll
        for (int q = 0; q < 4; q++) acc[t][q] = 0.f;

    const int arow = tid >> 1;
    const int ach = (tid & 1) * 16;
    const int gr_a = rowBase + arow;
    const bool a_ok = (gr_a < M);

    for (int c = 0; c < KC; c++) {
        const int gk = c * 32;
        const __half* Ap = (gk < 128) ? (A0 + (size_t)gr_a * 128 + gk + ach)
                                      : (A1 + (size_t)gr_a * 128 + (gk - 128) + ach);
#pragma unroll
        for (int i = 0; i < 2; i++) {
            uint4 v = a_ok ? *(const uint4*)(Ap + i * 8) : make_uint4(0, 0, 0, 0);
            *(uint4*)&sA[arow * ST + ach + i * 8] = v;
        }
        for (int idx = tid; idx < N * 4; idx += 256) {
            int n = idx >> 2, q = idx & 3;
            *(uint4*)&sBh[n * ST + q * 8] = *(const uint4*)(Bh + (size_t)n * KT + gk + q * 8);
            *(uint4*)&sBl[n * ST + q * 8] = *(const uint4*)(Bl + (size_t)n * KT + gk + q * 8);
        }
        __syncthreads();
#pragma unroll
        for (int ks = 0; ks < 2; ks++) {
            const int kb = ks * 16;
            const int am = wid * 16 + (lane & 7) + ((lane >> 3) & 1) * 8;
            const int ak = kb + (lane >> 4) * 8;
            uint32_t a0, a1, a2, a3;
            {
                uint32_t addr = s2u(&sA[am * ST + ak]);
                LDMX4(a0, a1, a2, a3, addr);
            }
            const int bn = (lane & 7) + (lane >> 4) * 8;
            const int bk = kb + ((lane >> 3) & 1) * 8;
#pragma unroll
            for (int p = 0; p < NT8 / 2; p++) {
                uint32_t bh0, bh1, bh2, bh3, bl0, bl1, bl2, bl3;
                uint32_t addr = s2u(&sBh[(p * 16 + bn) * ST + bk]);
                LDMX4(bh0, bh1, bh2, bh3, addr);
                addr = s2u(&sBl[(p * 16 + bn) * ST + bk]);
                LDMX4(bl0, bl1, bl2, bl3, addr);
                MMAF16(acc[2 * p + 0], a0, a1, a2, a3, bh0, bh1);
                MMAF16(acc[2 * p + 0], a0, a1, a2, a3, bl0, bl1);
                MMAF16(acc[2 * p + 1], a0, a1, a2, a3, bh2, bh3);
                MMAF16(acc[2 * p + 1], a0, a1, a2, a3, bl2, bl3);
            }
        }
        __syncthreads();
    }
    // ---- epilogue (all-fp16 outputs) ----
    const int r0 = rowBase + wid * 16 + (lane >> 2);
    const int col0 = (lane & 3) * 2;
#pragma unroll
    for (int t = 0; t < NT8; t++) {
        int col = t * 8 + col0;
        float2 v0 = make_float2(acc[t][0], acc[t][1]);
        float2 v1 = make_float2(acc[t][2], acc[t][3]);
        if (RELU) {
            float b0v = __ldg(bias + col), b1v = __ldg(bias + col + 1);
            v0.x = fmaxf(v0.x + b0v, 0.f); v0.y = fmaxf(v0.y + b1v, 0.f);
            v1.x = fmaxf(v1.x + b0v, 0.f); v1.y = fmaxf(v1.y + b1v, 0.f);
        }
        __half2 h0 = __floats2half2_rn(v0.x, v0.y);
        __half2 h1 = __floats2half2_rn(v1.x, v1.y);
        if (MODE == 0) {
            if (r0 < M)     *(uint32_t*)(Ch + (size_t)r0 * 128 + col) = *(uint32_t*)&h0;
            if (r0 + 8 < M) *(uint32_t*)(Ch + (size_t)(r0 + 8) * 128 + col) = *(uint32_t*)&h1;
        } else {
            __half* P0 = (col < 40) ? (Ch + (size_t)r0 * 40 + col)
                                    : (Cr + (size_t)r0 * 40 + col - 40);
            __half* P1 = (col < 40) ? (Ch + (size_t)(r0 + 8) * 40 + col)
                                    : (Cr + (size_t)(r0 + 8) * 40 + col - 40);
            if (r0 < M)     *(uint32_t*)P0 = *(uint32_t*)&h0;
            if (r0 + 8 < M) *(uint32_t*)P1 = *(uint32_t*)&h1;
        }
    }
}

// ---------------- fused layer-2 gather-mean + root + bias + log_softmax --------
// Also re-zeroes g_deg for the next run (invariant).
__global__ void final_k(const float* __restrict__ b2, float* __restrict__ out) {
    int gt = blockIdx.x * blockDim.x + threadIdx.x;
    int n = gt >> 5;
    int lane = gt & 31;
    if (n >= NN) return;
    int start = g_rowstart[n];
    int deg = g_deg[n];
    int c = lane * 2;
    float2 acc = make_float2(0.f, 0.f);
    if (lane < 20) {
        int i = 0;
        for (; i + 1 < deg; i += 2) {
            int s0 = __ldg(g_csr + start + i);
            int s1 = __ldg(g_csr + start + i + 1);
            uint32_t r0 = *(const uint32_t*)(g_trh + (size_t)s0 * 40 + c);
            uint32_t r1 = *(const uint32_t*)(g_trh + (size_t)s1 * 40 + c);
            float2 v0 = __half22float2(*(__half2*)&r0);
            float2 v1 = __half22float2(*(__half2*)&r1);
            acc.x += v0.x + v1.x;
            acc.y += v0.y + v1.y;
        }
        if (i < deg) {
            int s0 = __ldg(g_csr + start + i);
            uint32_t r0 = *(const uint32_t*)(g_trh + (size_t)s0 * 40 + c);
            float2 v0 = __half22float2(*(__half2*)&r0);
            acc.x += v0.x;
            acc.y += v0.y;
        }
    }
    if (lane == 0) g_deg[n] = 0; // restore invariant for next run
    float inv = 1.0f / fmaxf((float)deg, 1.0f);
    float e0 = -3.4e38f, e1 = -3.4e38f;
    if (lane < 20) {
        uint32_t rr = *(const uint32_t*)(g_trr + (size_t)n * 40 + c);
        float2 root = __half22float2(*(__half2*)&rr);
        e0 = acc.x * inv + root.x + b2[c];
        e1 = acc.y * inv + root.y + b2[c + 1];
    }
    float m = fmaxf(e0, e1);
#pragma unroll
    for (int o = 16; o > 0; o >>= 1) m = fmaxf(m, __shfl_xor_sync(0xffffffffu, m, o));
    float s = (lane < 20) ? (expf(e0 - m) + expf(e1 - m)) : 0.f;
#pragma unroll
    for (int o = 16; o > 0; o >>= 1) s += __shfl_xor_sync(0xffffffffu, s, o);
    float lse = m + logf(s);
    if (lane < 20) {
        float2 o2;
        o2.x = e0 - lse;
        o2.y = e1 - lse;
        *(float2*)(out + (size_t)n * 40 + c) = o2;
    }
}

// ---------------- launch ----------------
extern "C" void kernel_launch(void* const* d_in, const int* in_sizes, int n_in,
                              void* d_out, int out_size) {
    const float* x   = (const float*)d_in[0];
    const void* ei   = d_in[1];
    const float* W1l = (const float*)d_in[2];
    const float* W1r = (const float*)d_in[3];
    const float* b1  = (const float*)d_in[4];
    const float* W2l = (const float*)d_in[5];
    const float* W2r = (const float*)d_in[6];
    const float* b2  = (const float*)d_in[7];
    float* out       = (float*)d_out;

    __half *xh, *a1h, *hh, *trh, *trr;
    unsigned short *w1h, *w1lo, *w2h, *w2lo;
    cudaGetSymbolAddress((void**)&xh, g_xh);
    cudaGetSymbolAddress((void**)&a1h, g_a1h);
    cudaGetSymbolAddress((void**)&hh, g_hh);
    cudaGetSymbolAddress((void**)&trh, g_trh);
    cudaGetSymbolAddress((void**)&trr, g_trr);
    cudaGetSymbolAddress((void**)&w1h, g_w1h);
    cudaGetSymbolAddress((void**)&w1lo, g_w1lo);
    cudaGetSymbolAddress((void**)&w2h, g_w2h);
    cudaGetSymbolAddress((void**)&w2lo, g_w2lo);

    const int mtiles = (NN + 127) / 128; // 782

    fused0_k<<<(NN * 32 + 255) / 256, 256>>>(x, ei, W1l, W1r, W2l, W2r);
    scan1_k<<<NB, 1024>>>();
    scan23_k<<<(NN + 255) / 256, 256>>>();
    fill_k<<<(NE + 255) / 256, 256>>>(ei);
    agg1_k<<<(NN * 32 + 255) / 256, 256>>>();
    gemm_mma<128, 256, true, 0><<<mtiles, 256>>>(NN, a1h, xh, w1h, w1lo, b1, hh, nullptr);
    gemm_mma<80, 128, false, 1><<<mtiles, 256>>>(NN, hh, hh, w2h, w2lo, nullptr, trh, trr);
    final_k<<<(NN * 32 + 255) / 256, 256>>>(b2, out);
}